// round 5
// baseline (speedup 1.0000x reference)
#include <cuda_runtime.h>
#include <math.h>

#define EMB   2048
#define NH    16
#define DH    128
#define BSZ   4
#define TLEN  2048
#define MROWS (BSZ*TLEN)   // 8192

// ---------------- scratch (static device globals; no allocations) ----------
__device__ float g_Q[MROWS*EMB];   // [B*T, EMB]  (col = h*DH + d)
__device__ float g_K[MROWS*DH];    // [B*T, DH]
__device__ float g_V[MROWS*DH];    // [B*T, DH]
__device__ float g_A[MROWS*EMB];   // attention output, same layout as g_Q

// ---------------- fused QKV SGEMM -----------------------------------------
// C = X @ W.  grid.x: 0..15 -> Wq col-tiles, 16 -> Wk, 17 -> Wv.
// BM=BN=128, BK=8, 256 threads, 8x8 per thread.
#define BM 128
#define BN 128
#define BK 8

__global__ __launch_bounds__(256, 2)
void qkv_gemm(const float* __restrict__ X,
              const float* __restrict__ Wq,
              const float* __restrict__ Wk,
              const float* __restrict__ Wv) {
    __shared__ float As[BK][BM];
    __shared__ float Bs[BK][BN];

    const int bx = blockIdx.x, by = blockIdx.y;
    const float* Bp;
    float* Cp;
    int n, col0;
    if (bx < 16)       { Bp = Wq; Cp = g_Q; n = EMB; col0 = bx * BN; }
    else if (bx == 16) { Bp = Wk; Cp = g_K; n = DH;  col0 = 0; }
    else               { Bp = Wv; Cp = g_V; n = DH;  col0 = 0; }

    const int tid = threadIdx.x;
    const int tx = tid & 15, ty = tid >> 4;
    const int row0 = by * BM;

    const int arow = tid >> 1;          // 0..127
    const int acol = (tid & 1) * 4;     // 0 or 4
    const int brow = tid >> 5;          // 0..7
    const int bcol = (tid & 31) * 4;    // 0..124

    float acc[8][8];
    #pragma unroll
    for (int i = 0; i < 8; i++)
        #pragma unroll
        for (int j = 0; j < 8; j++) acc[i][j] = 0.0f;

    for (int k0 = 0; k0 < EMB; k0 += BK) {
        float4 av = *(const float4*)&X[(row0 + arow) * EMB + k0 + acol];
        As[acol + 0][arow] = av.x;
        As[acol + 1][arow] = av.y;
        As[acol + 2][arow] = av.z;
        As[acol + 3][arow] = av.w;
        float4 bv = *(const float4*)&Bp[(k0 + brow) * n + col0 + bcol];
        *(float4*)&Bs[brow][bcol] = bv;
        __syncthreads();

        #pragma unroll
        for (int k = 0; k < BK; k++) {
            float4 a0 = *(const float4*)&As[k][ty * 8];
            float4 a1 = *(const float4*)&As[k][ty * 8 + 4];
            float4 b0 = *(const float4*)&Bs[k][tx * 8];
            float4 b1 = *(const float4*)&Bs[k][tx * 8 + 4];
            float a[8] = {a0.x, a0.y, a0.z, a0.w, a1.x, a1.y, a1.z, a1.w};
            float b[8] = {b0.x, b0.y, b0.z, b0.w, b1.x, b1.y, b1.z, b1.w};
            #pragma unroll
            for (int i = 0; i < 8; i++)
                #pragma unroll
                for (int j = 0; j < 8; j++)
                    acc[i][j] += a[i] * b[j];
        }
        __syncthreads();
    }

    #pragma unroll
    for (int i = 0; i < 8; i++) {
        int r = row0 + ty * 8 + i;
        float4 o0 = make_float4(acc[i][0], acc[i][1], acc[i][2], acc[i][3]);
        float4 o1 = make_float4(acc[i][4], acc[i][5], acc[i][6], acc[i][7]);
        *(float4*)&Cp[r * n + col0 + tx * 8]     = o0;
        *(float4*)&Cp[r * n + col0 + tx * 8 + 4] = o1;
    }
}

// ---------------- output SGEMM with bias ----------------------------------
__global__ __launch_bounds__(256, 2)
void out_gemm(const float* __restrict__ Wo,
              const float* __restrict__ bo,
              float* __restrict__ out) {
    __shared__ float As[BK][BM];
    __shared__ float Bs[BK][BN];

    const int bx = blockIdx.x, by = blockIdx.y;
    const int col0 = bx * BN;
    const int tid = threadIdx.x;
    const int tx = tid & 15, ty = tid >> 4;
    const int row0 = by * BM;

    const int arow = tid >> 1;
    const int acol = (tid & 1) * 4;
    const int brow = tid >> 5;
    const int bcol = (tid & 31) * 4;

    float acc[8][8];
    #pragma unroll
    for (int i = 0; i < 8; i++)
        #pragma unroll
        for (int j = 0; j < 8; j++) acc[i][j] = 0.0f;

    for (int k0 = 0; k0 < EMB; k0 += BK) {
        float4 av = *(const float4*)&g_A[(row0 + arow) * EMB + k0 + acol];
        As[acol + 0][arow] = av.x;
        As[acol + 1][arow] = av.y;
        As[acol + 2][arow] = av.z;
        As[acol + 3][arow] = av.w;
        float4 bv = *(const float4*)&Wo[(k0 + brow) * EMB + col0 + bcol];
        *(float4*)&Bs[brow][bcol] = bv;
        __syncthreads();

        #pragma unroll
        for (int k = 0; k < BK; k++) {
            float4 a0 = *(const float4*)&As[k][ty * 8];
            float4 a1 = *(const float4*)&As[k][ty * 8 + 4];
            float4 b0 = *(const float4*)&Bs[k][tx * 8];
            float4 b1 = *(const float4*)&Bs[k][tx * 8 + 4];
            float a[8] = {a0.x, a0.y, a0.z, a0.w, a1.x, a1.y, a1.z, a1.w};
            float b[8] = {b0.x, b0.y, b0.z, b0.w, b1.x, b1.y, b1.z, b1.w};
            #pragma unroll
            for (int i = 0; i < 8; i++)
                #pragma unroll
                for (int j = 0; j < 8; j++)
                    acc[i][j] += a[i] * b[j];
        }
        __syncthreads();
    }

    float4 bb0 = *(const float4*)&bo[col0 + tx * 8];
    float4 bb1 = *(const float4*)&bo[col0 + tx * 8 + 4];
    #pragma unroll
    for (int i = 0; i < 8; i++) {
        int r = row0 + ty * 8 + i;
        float4 o0 = make_float4(acc[i][0] + bb0.x, acc[i][1] + bb0.y,
                                acc[i][2] + bb0.z, acc[i][3] + bb0.w);
        float4 o1 = make_float4(acc[i][4] + bb1.x, acc[i][5] + bb1.y,
                                acc[i][6] + bb1.z, acc[i][7] + bb1.w);
        *(float4*)&out[r * EMB + col0 + tx * 8]     = o0;
        *(float4*)&out[r * EMB + col0 + tx * 8 + 4] = o1;
    }
}

// ---------------- causal MQA flash attention ------------------------------
// Grid: (T/64, H, B).  256 threads.  64-row Q tile, 64-key KV tiles.
// Thread map: ty=tid/16 owns rows ty*4..+3 ; tx=tid%16 owns S cols tx*4..+3
// and O cols tx*8..+7.
#define BR 64
#define BC 64
#define KT_PAD 68   // Kts row pad (BC+4): 2-way conflicts max
#define PS_PAD 68

#define ATTN_SMEM ((BR*DH + DH*KT_PAD + BC*DH + BR*PS_PAD) * (int)sizeof(float))

__global__ __launch_bounds__(256, 1)
void attn_kernel() {
    extern __shared__ float sm[];
    float* Qs  = sm;                    // [BR][DH]
    float* Kts = Qs  + BR * DH;         // [DH][KT_PAD]   (transposed K)
    float* Vs  = Kts + DH * KT_PAD;     // [BC][DH]
    float* Ps  = Vs  + BC * DH;         // [BR][PS_PAD]

    const int qt  = blockIdx.x;         // 0..31
    const int h   = blockIdx.y;
    const int b   = blockIdx.z;
    const int tid = threadIdx.x;
    const int tx  = tid & 15, ty = tid >> 4;
    const int q0  = qt * BR;

    // ---- load Q tile (once) ----
    const float* Qg = g_Q + (b * TLEN + q0) * EMB + h * DH;
    for (int f = tid; f < BR * (DH / 4); f += 256) {
        int r = f >> 5;           // row (32 float4/row)
        int d4 = (f & 31) << 2;
        *(float4*)&Qs[r * DH + d4] = *(const float4*)&Qg[r * EMB + d4];
    }

    float o[4][8];
    float m[4], l[4];
    #pragma unroll
    for (int i = 0; i < 4; i++) {
        m[i] = -1e30f; l[i] = 0.0f;
        #pragma unroll
        for (int c = 0; c < 8; c++) o[i][c] = 0.0f;
    }

    const float scale = 0.08838834764831845f;  // 1/sqrt(128)

    for (int jt = 0; jt <= qt; jt++) {
        const int j0 = jt * BC;
        __syncthreads();   // previous tile's Ps/Vs reads done; Qs load done (jt=0)

        // ---- load K (transposed) and V tiles ----
        const float* Kg = g_K + (b * TLEN + j0) * DH;
        const float* Vg = g_V + (b * TLEN + j0) * DH;
        for (int f = tid; f < BC * (DH / 4); f += 256) {
            int r = f >> 5;
            int d4 = (f & 31) << 2;
            float4 kv = *(const float4*)&Kg[r * DH + d4];
            Kts[(d4 + 0) * KT_PAD + r] = kv.x;
            Kts[(d4 + 1) * KT_PAD + r] = kv.y;
            Kts[(d4 + 2) * KT_PAD + r] = kv.z;
            Kts[(d4 + 3) * KT_PAD + r] = kv.w;
            *(float4*)&Vs[r * DH + d4] = *(const float4*)&Vg[r * DH + d4];
        }
        __syncthreads();

        // ---- S = scale * Q @ K^T  (4x4 per thread) ----
        float s[4][4];
        #pragma unroll
        for (int i = 0; i < 4; i++)
            #pragma unroll
            for (int j = 0; j < 4; j++) s[i][j] = 0.0f;

        #pragma unroll 4
        for (int d = 0; d < DH; d++) {
            float q[4], kk[4];
            #pragma unroll
            for (int i = 0; i < 4; i++) q[i] = Qs[(ty * 4 + i) * DH + d];
            #pragma unroll
            for (int j = 0; j < 4; j++) kk[j] = Kts[d * KT_PAD + tx * 4 + j];
            #pragma unroll
            for (int i = 0; i < 4; i++)
                #pragma unroll
                for (int j = 0; j < 4; j++)
                    s[i][j] += q[i] * kk[j];
        }

        const bool diag = (jt == qt);
        #pragma unroll
        for (int i = 0; i < 4; i++) {
            int ri = ty * 4 + i;
            #pragma unroll
            for (int j = 0; j < 4; j++) {
                float v = s[i][j] * scale;
                if (diag && (tx * 4 + j) > ri) v = -1e30f;
                s[i][j] = v;
            }
        }

        // ---- online softmax update ----
        #pragma unroll
        for (int i = 0; i < 4; i++) {
            float tm = fmaxf(fmaxf(s[i][0], s[i][1]), fmaxf(s[i][2], s[i][3]));
            #pragma unroll
            for (int off = 8; off; off >>= 1)
                tm = fmaxf(tm, __shfl_xor_sync(0xffffffffu, tm, off));
            float mn = fmaxf(m[i], tm);
            float al = expf(m[i] - mn);
            float rs = 0.0f;
            #pragma unroll
            for (int j = 0; j < 4; j++) {
                float p = expf(s[i][j] - mn);
                s[i][j] = p;
                rs += p;
            }
            #pragma unroll
            for (int off = 8; off; off >>= 1)
                rs += __shfl_xor_sync(0xffffffffu, rs, off);
            l[i] = l[i] * al + rs;
            m[i] = mn;
            #pragma unroll
            for (int c = 0; c < 8; c++) o[i][c] *= al;
            #pragma unroll
            for (int j = 0; j < 4; j++)
                Ps[(ty * 4 + i) * PS_PAD + tx * 4 + j] = s[i][j];
        }
        __syncthreads();

        // ---- O += P @ V ----
        #pragma unroll 2
        for (int j = 0; j < BC; j++) {
            float4 v0 = *(const float4*)&Vs[j * DH + tx * 8];
            float4 v1 = *(const float4*)&Vs[j * DH + tx * 8 + 4];
            float p[4];
            #pragma unroll
            for (int i = 0; i < 4; i++) p[i] = Ps[(ty * 4 + i) * PS_PAD + j];
            #pragma unroll
            for (int i = 0; i < 4; i++) {
                o[i][0] += p[i] * v0.x;  o[i][1] += p[i] * v0.y;
                o[i][2] += p[i] * v0.z;  o[i][3] += p[i] * v0.w;
                o[i][4] += p[i] * v1.x;  o[i][5] += p[i] * v1.y;
                o[i][6] += p[i] * v1.z;  o[i][7] += p[i] * v1.w;
            }
        }
    }

    // ---- epilogue: normalize and write ----
    float* Ag = g_A + (b * TLEN + q0) * EMB + h * DH;
    #pragma unroll
    for (int i = 0; i < 4; i++) {
        float inv = 1.0f / l[i];
        int r = ty * 4 + i;
        float4 w0 = make_float4(o[i][0] * inv, o[i][1] * inv,
                                o[i][2] * inv, o[i][3] * inv);
        float4 w1 = make_float4(o[i][4] * inv, o[i][5] * inv,
                                o[i][6] * inv, o[i][7] * inv);
        *(float4*)&Ag[r * EMB + tx * 8]     = w0;
        *(float4*)&Ag[r * EMB + tx * 8 + 4] = w1;
    }
}

// ---------------- launch ---------------------------------------------------
extern "C" void kernel_launch(void* const* d_in, const int* in_sizes, int n_in,
                              void* d_out, int out_size) {
    const float* x  = (const float*)d_in[0];
    const float* Wq = (const float*)d_in[1];
    const float* Wk = (const float*)d_in[2];
    const float* Wv = (const float*)d_in[3];
    const float* Wo = (const float*)d_in[4];
    const float* bo = (const float*)d_in[5];
    float* out = (float*)d_out;

    (void)in_sizes; (void)n_in; (void)out_size;

    // 1) fused QKV projection
    qkv_gemm<<<dim3(18, MROWS / BM), 256>>>(x, Wq, Wk, Wv);

    // 2) causal MQA flash attention
    cudaFuncSetAttribute(attn_kernel,
                         cudaFuncAttributeMaxDynamicSharedMemorySize, ATTN_SMEM);
    attn_kernel<<<dim3(TLEN / BR, NH, BSZ), 256, ATTN_SMEM>>>();

    // 3) output projection + bias
    out_gemm<<<dim3(EMB / BN, MROWS / BM), 256>>>(Wo, bo, out);
}

// round 10
// speedup vs baseline: 2.6002x; 2.6002x over previous
#include <cuda_runtime.h>
#include <cuda_bf16.h>
#include <stdint.h>
#include <math.h>

#define EMB   2048
#define NH    16
#define DH    128
#define BSZ   4
#define TLEN  2048
#define MROWS (BSZ*TLEN)   // 8192
#define NQKV  2304         // 2048 (Q heads) + 128 (K) + 128 (V)
#define GK    2048         // GEMM K depth

// ---------------- scratch (static device globals; no allocations) ----------
__device__ float         g_C[MROWS*NQKV];       // QKV output [8192][2304]
__device__ float         g_A[MROWS*EMB];        // attention output
__device__ __nv_bfloat16 g_Xh[MROWS*GK], g_Xl[MROWS*GK];
__device__ __nv_bfloat16 g_Ah[MROWS*GK], g_Al[MROWS*GK];
__device__ __nv_bfloat16 g_Wth[NQKV*GK], g_Wtl[NQKV*GK];    // [Wq|Wk|Wv]^T [N,K]
__device__ __nv_bfloat16 g_Woth[EMB*GK], g_Wotl[EMB*GK];    // Wo^T [N,K]

// ==================== helpers ==============================================
__device__ __forceinline__ uint32_t smem_u32(const void* p) {
    uint32_t a;
    asm("{ .reg .u64 t; cvta.to.shared.u64 t, %1; cvt.u32.u64 %0, t; }"
        : "=r"(a) : "l"(p));
    return a;
}
__device__ __forceinline__ void cp_async16(uint32_t dst, const void* src) {
    asm volatile("cp.async.cg.shared.global [%0], [%1], 16;\n"
                 :: "r"(dst), "l"(src));
}
#define CP_COMMIT()  asm volatile("cp.async.commit_group;\n" ::: "memory")
#define CP_WAIT(n)   asm volatile("cp.async.wait_group %0;\n" :: "n"(n) : "memory")

__device__ __forceinline__ void ldm_x4(uint32_t& r0, uint32_t& r1,
                                       uint32_t& r2, uint32_t& r3, uint32_t a) {
    asm volatile("ldmatrix.sync.aligned.m8n8.x4.shared.b16 {%0,%1,%2,%3}, [%4];"
                 : "=r"(r0), "=r"(r1), "=r"(r2), "=r"(r3) : "r"(a));
}
__device__ __forceinline__ void mma_bf16(float* c, const uint32_t* a,
                                         uint32_t b0, uint32_t b1) {
    asm volatile(
        "mma.sync.aligned.m16n8k16.row.col.f32.bf16.bf16.f32 "
        "{%0,%1,%2,%3}, {%4,%5,%6,%7}, {%8,%9}, {%0,%1,%2,%3};"
        : "+f"(c[0]), "+f"(c[1]), "+f"(c[2]), "+f"(c[3])
        : "r"(a[0]), "r"(a[1]), "r"(a[2]), "r"(a[3]), "r"(b0), "r"(b1));
}

// ==================== conversion kernels ===================================
__device__ __forceinline__ void split1(float v, __nv_bfloat16& h, __nv_bfloat16& l) {
    h = __float2bfloat16(v);
    l = __float2bfloat16(v - __bfloat162float(h));
}

__global__ void split_vec(const float* __restrict__ src,
                          __nv_bfloat16* __restrict__ h,
                          __nv_bfloat16* __restrict__ l, int n4) {
    int i = blockIdx.x * blockDim.x + threadIdx.x;
    int stride = gridDim.x * blockDim.x;
    __nv_bfloat162* H = (__nv_bfloat162*)h;
    __nv_bfloat162* L = (__nv_bfloat162*)l;
    for (; i < n4; i += stride) {
        float4 v = ((const float4*)src)[i];
        __nv_bfloat16 h0, l0, h1, l1, h2, l2, h3, l3;
        split1(v.x, h0, l0); split1(v.y, h1, l1);
        split1(v.z, h2, l2); split1(v.w, h3, l3);
        H[2*i]     = __halves2bfloat162(h0, h1);
        H[2*i + 1] = __halves2bfloat162(h2, h3);
        L[2*i]     = __halves2bfloat162(l0, l1);
        L[2*i + 1] = __halves2bfloat162(l2, l3);
    }
}

// transpose + split: src [2048(K)][N] fp32 -> dest [(rowOff+n)][k] bf16, ld 2048
__global__ void tsplit(const float* __restrict__ src,
                       __nv_bfloat16* __restrict__ dh,
                       __nv_bfloat16* __restrict__ dl, int N, int rowOff) {
    __shared__ float t[32][33];
    int n0 = blockIdx.x * 32, k0 = blockIdx.y * 32;
    int tx = threadIdx.x, ty = threadIdx.y;     // 32 x 8
    #pragma unroll
    for (int r = 0; r < 4; r++)
        t[ty + r*8][tx] = src[(size_t)(k0 + ty + r*8) * N + n0 + tx];
    __syncthreads();
    #pragma unroll
    for (int r = 0; r < 4; r++) {
        int n = n0 + ty + r*8, k = k0 + tx;
        float v = t[tx][ty + r*8];
        __nv_bfloat16 h, l; split1(v, h, l);
        size_t o = (size_t)(n + rowOff) * GK + k;
        dh[o] = h; dl[o] = l;
    }
}

// ==================== mma.sync split-bf16 GEMM =============================
// C[M,N] = A[M,K] * B[N,K]^T, fp32-accurate via 3-term bf16 split.
// CTA: 128x128 tile, 8 warps (2x4), warp tile 64x32. K-chunk 64, 2-stage cp.async.
#define KC      64
#define LDSE    72                     // bf16 elems per smem row (64 + 8 pad)
#define TILE_B  (128*LDSE*2)           // 18432 B
#define STAGE_B (4*TILE_B)             // Ah,Al,Bh,Bl = 73728 B
#define GSMEM   (2*STAGE_B)            // 147456 B
#define NCHUNK  (GK/KC)                // 32

__global__ __launch_bounds__(256)
void gemm_mma(const __nv_bfloat16* __restrict__ Ah, const __nv_bfloat16* __restrict__ Al,
              const __nv_bfloat16* __restrict__ Bh, const __nv_bfloat16* __restrict__ Bl,
              float* __restrict__ C, const float* __restrict__ bias, int ldc) {
    extern __shared__ char smem[];
    const uint32_t sb = smem_u32(smem);

    const int tid  = threadIdx.x;
    const int wid  = tid >> 5;
    const int lane = tid & 31;
    const int wm   = wid >> 2;          // 0..1 : warp row (64 rows)
    const int wn   = wid & 3;           // 0..3 : warp col (32 cols)
    const int row0 = blockIdx.y * 128;
    const int n0   = blockIdx.x * 128;

    const __nv_bfloat16* pAh = Ah + (size_t)row0 * GK;
    const __nv_bfloat16* pAl = Al + (size_t)row0 * GK;
    const __nv_bfloat16* pBh = Bh + (size_t)n0 * GK;
    const __nv_bfloat16* pBl = Bl + (size_t)n0 * GK;

    // per-thread cp.async mapping: 1024 16B chunks per tile, 4 iters x 256 thr
    const int cr = tid >> 3;            // base row 0..31 step (handled by iter)
    const int cc = tid & 7;             // 16B chunk in row

    float acc[4][4][4];
    #pragma unroll
    for (int i = 0; i < 4; i++)
        #pragma unroll
        for (int j = 0; j < 4; j++)
            #pragma unroll
            for (int r = 0; r < 4; r++) acc[i][j][r] = 0.0f;

    // ldmatrix lane addressing (byte offsets within a tile)
    const int a_row = wm * 64 + (lane & 15);            // + mi*16
    const int a_col = (lane >> 4) * 8;                  // + ks*16
    const int b_g   = lane >> 3;                        // group 0..3
    const int b_row = wn * 32 + ((b_g >> 1) * 8) + (lane & 7);  // + nb(0/16)
    const int b_col = (b_g & 1) * 8;                    // + ks*16

    auto load_stage = [&](int s, int c) {
        const uint32_t st = sb + s * STAGE_B;
        const int k0 = c * KC;
        #pragma unroll
        for (int it = 0; it < 4; ++it) {
            int r = cr + it * 32;
            uint32_t so = (uint32_t)(r * (LDSE*2) + cc * 16);
            size_t   go = (size_t)r * GK + k0 + cc * 8;
            cp_async16(st + 0*TILE_B + so, pAh + go);
            cp_async16(st + 1*TILE_B + so, pAl + go);
            cp_async16(st + 2*TILE_B + so, pBh + go);
            cp_async16(st + 3*TILE_B + so, pBl + go);
        }
        CP_COMMIT();
    };

    load_stage(0, 0);

    for (int c = 0; c < NCHUNK; ++c) {
        if (c + 1 < NCHUNK) { load_stage((c + 1) & 1, c + 1); CP_WAIT(1); }
        else                { CP_WAIT(0); }
        __syncthreads();

        const uint32_t st = sb + (c & 1) * STAGE_B;
        const uint32_t aBh = st + 0*TILE_B;
        const uint32_t aBl_= st + 1*TILE_B;
        const uint32_t bBh = st + 2*TILE_B;
        const uint32_t bBl = st + 3*TILE_B;

        #pragma unroll
        for (int ks = 0; ks < 4; ++ks) {
            uint32_t ah[4][4], al[4][4];
            #pragma unroll
            for (int mi = 0; mi < 4; ++mi) {
                uint32_t off = (uint32_t)((a_row + mi*16) * (LDSE*2)
                                          + (a_col + ks*16) * 2);
                ldm_x4(ah[mi][0], ah[mi][1], ah[mi][2], ah[mi][3], aBh + off);
                ldm_x4(al[mi][0], al[mi][1], al[mi][2], al[mi][3], aBl_ + off);
            }
            uint32_t bh[8], bl[8];
            #pragma unroll
            for (int nb = 0; nb < 2; ++nb) {
                uint32_t off = (uint32_t)((b_row + nb*16) * (LDSE*2)
                                          + (b_col + ks*16) * 2);
                ldm_x4(bh[nb*4+0], bh[nb*4+1], bh[nb*4+2], bh[nb*4+3], bBh + off);
                ldm_x4(bl[nb*4+0], bl[nb*4+1], bl[nb*4+2], bl[nb*4+3], bBl + off);
            }
            #pragma unroll
            for (int mi = 0; mi < 4; ++mi) {
                #pragma unroll
                for (int ni = 0; ni < 4; ++ni) {
                    uint32_t b0h = bh[ni*2], b1h = bh[ni*2+1];
                    uint32_t b0l = bl[ni*2], b1l = bl[ni*2+1];
                    mma_bf16(acc[mi][ni], ah[mi], b0h, b1h);   // Ah*Bh
                    mma_bf16(acc[mi][ni], ah[mi], b0l, b1l);   // Ah*Bl
                    mma_bf16(acc[mi][ni], al[mi], b0h, b1h);   // Al*Bh
                }
            }
        }
        __syncthreads();
    }

    // epilogue: direct register -> gmem (float2), optional bias
    const int er = lane >> 2;           // 0..7
    const int ec = (lane & 3) * 2;      // 0,2,4,6
    #pragma unroll
    for (int mi = 0; mi < 4; ++mi) {
        #pragma unroll
        for (int ni = 0; ni < 4; ++ni) {
            int gr = row0 + wm*64 + mi*16 + er;
            int gc = n0 + wn*32 + ni*8 + ec;
            float bx = 0.f, by = 0.f;
            if (bias) { bx = bias[gc]; by = bias[gc + 1]; }
            float2 v0 = make_float2(acc[mi][ni][0] + bx, acc[mi][ni][1] + by);
            float2 v1 = make_float2(acc[mi][ni][2] + bx, acc[mi][ni][3] + by);
            *(float2*)&C[(size_t)gr * ldc + gc]       = v0;
            *(float2*)&C[(size_t)(gr + 8) * ldc + gc] = v1;
        }
    }
}

// ==================== causal MQA flash attention (SIMT fp32) ===============
#define BR 64
#define BC 64
#define KT_PAD 68
#define PS_PAD 68
#define ATTN_SMEM ((BR*DH + DH*KT_PAD + BC*DH + BR*PS_PAD) * (int)sizeof(float))

__global__ __launch_bounds__(256, 1)
void attn_kernel() {
    extern __shared__ float sm[];
    float* Qs  = sm;
    float* Kts = Qs  + BR * DH;
    float* Vs  = Kts + DH * KT_PAD;
    float* Ps  = Vs  + BC * DH;

    const int qt  = blockIdx.x;
    const int h   = blockIdx.y;
    const int b   = blockIdx.z;
    const int tid = threadIdx.x;
    const int tx  = tid & 15, ty = tid >> 4;
    const int q0  = qt * BR;

    const float* Qg = g_C + (size_t)(b * TLEN + q0) * NQKV + h * DH;
    for (int f = tid; f < BR * (DH / 4); f += 256) {
        int r = f >> 5;
        int d4 = (f & 31) << 2;
        *(float4*)&Qs[r * DH + d4] = *(const float4*)&Qg[(size_t)r * NQKV + d4];
    }

    float o[4][8];
    float m[4], l[4];
    #pragma unroll
    for (int i = 0; i < 4; i++) {
        m[i] = -1e30f; l[i] = 0.0f;
        #pragma unroll
        for (int c = 0; c < 8; c++) o[i][c] = 0.0f;
    }

    const float scale = 0.08838834764831845f;  // 1/sqrt(128)

    for (int jt = 0; jt <= qt; jt++) {
        const int j0 = jt * BC;
        __syncthreads();

        const float* Kg = g_C + (size_t)(b * TLEN + j0) * NQKV + 2048;
        const float* Vg = g_C + (size_t)(b * TLEN + j0) * NQKV + 2176;
        for (int f = tid; f < BC * (DH / 4); f += 256) {
            int r = f >> 5;
            int d4 = (f & 31) << 2;
            float4 kv = *(const float4*)&Kg[(size_t)r * NQKV + d4];
            Kts[(d4 + 0) * KT_PAD + r] = kv.x;
            Kts[(d4 + 1) * KT_PAD + r] = kv.y;
            Kts[(d4 + 2) * KT_PAD + r] = kv.z;
            Kts[(d4 + 3) * KT_PAD + r] = kv.w;
            *(float4*)&Vs[r * DH + d4] = *(const float4*)&Vg[(size_t)r * NQKV + d4];
        }
        __syncthreads();

        float s[4][4];
        #pragma unroll
        for (int i = 0; i < 4; i++)
            #pragma unroll
            for (int j = 0; j < 4; j++) s[i][j] = 0.0f;

        #pragma unroll 4
        for (int d = 0; d < DH; d++) {
            float q[4], kk[4];
            #pragma unroll
            for (int i = 0; i < 4; i++) q[i] = Qs[(ty * 4 + i) * DH + d];
            #pragma unroll
            for (int j = 0; j < 4; j++) kk[j] = Kts[d * KT_PAD + tx * 4 + j];
            #pragma unroll
            for (int i = 0; i < 4; i++)
                #pragma unroll
                for (int j = 0; j < 4; j++)
                    s[i][j] += q[i] * kk[j];
        }

        const bool diag = (jt == qt);
        #pragma unroll
        for (int i = 0; i < 4; i++) {
            int ri = ty * 4 + i;
            #pragma unroll
            for (int j = 0; j < 4; j++) {
                float v = s[i][j] * scale;
                if (diag && (tx * 4 + j) > ri) v = -1e30f;
                s[i][j] = v;
            }
        }

        #pragma unroll
        for (int i = 0; i < 4; i++) {
            float tm = fmaxf(fmaxf(s[i][0], s[i][1]), fmaxf(s[i][2], s[i][3]));
            #pragma unroll
            for (int off = 8; off; off >>= 1)
                tm = fmaxf(tm, __shfl_xor_sync(0xffffffffu, tm, off));
            float mn = fmaxf(m[i], tm);
            float al = __expf(m[i] - mn);
            float rs = 0.0f;
            #pragma unroll
            for (int j = 0; j < 4; j++) {
                float p = __expf(s[i][j] - mn);
                s[i][j] = p;
                rs += p;
            }
            #pragma unroll
            for (int off = 8; off; off >>= 1)
                rs += __shfl_xor_sync(0xffffffffu, rs, off);
            l[i] = l[i] * al + rs;
            m[i] = mn;
            #pragma unroll
            for (int c = 0; c < 8; c++) o[i][c] *= al;
            #pragma unroll
            for (int j = 0; j < 4; j++)
                Ps[(ty * 4 + i) * PS_PAD + tx * 4 + j] = s[i][j];
        }
        __syncthreads();

        #pragma unroll 2
        for (int j = 0; j < BC; j++) {
            float4 v0 = *(const float4*)&Vs[j * DH + tx * 8];
            float4 v1 = *(const float4*)&Vs[j * DH + tx * 8 + 4];
            float p[4];
            #pragma unroll
            for (int i = 0; i < 4; i++) p[i] = Ps[(ty * 4 + i) * PS_PAD + j];
            #pragma unroll
            for (int i = 0; i < 4; i++) {
                o[i][0] += p[i] * v0.x;  o[i][1] += p[i] * v0.y;
                o[i][2] += p[i] * v0.z;  o[i][3] += p[i] * v0.w;
                o[i][4] += p[i] * v1.x;  o[i][5] += p[i] * v1.y;
                o[i][6] += p[i] * v1.z;  o[i][7] += p[i] * v1.w;
            }
        }
    }

    float* Ag = g_A + (size_t)(b * TLEN + q0) * EMB + h * DH;
    #pragma unroll
    for (int i = 0; i < 4; i++) {
        float inv = 1.0f / l[i];
        int r = ty * 4 + i;
        float4 w0 = make_float4(o[i][0] * inv, o[i][1] * inv,
                                o[i][2] * inv, o[i][3] * inv);
        float4 w1 = make_float4(o[i][4] * inv, o[i][5] * inv,
                                o[i][6] * inv, o[i][7] * inv);
        *(float4*)&Ag[(size_t)r * EMB + tx * 8]     = w0;
        *(float4*)&Ag[(size_t)r * EMB + tx * 8 + 4] = w1;
    }
}

// ==================== launch ===============================================
extern "C" void kernel_launch(void* const* d_in, const int* in_sizes, int n_in,
                              void* d_out, int out_size) {
    const float* x  = (const float*)d_in[0];
    const float* Wq = (const float*)d_in[1];
    const float* Wk = (const float*)d_in[2];
    const float* Wv = (const float*)d_in[3];
    const float* Wo = (const float*)d_in[4];
    const float* bo = (const float*)d_in[5];
    float* out = (float*)d_out;
    (void)in_sizes; (void)n_in; (void)out_size;

    void *pXh, *pXl, *pAh, *pAl, *pWth, *pWtl, *pWoth, *pWotl, *pC, *pA;
    cudaGetSymbolAddress(&pXh, g_Xh);   cudaGetSymbolAddress(&pXl, g_Xl);
    cudaGetSymbolAddress(&pAh, g_Ah);   cudaGetSymbolAddress(&pAl, g_Al);
    cudaGetSymbolAddress(&pWth, g_Wth); cudaGetSymbolAddress(&pWtl, g_Wtl);
    cudaGetSymbolAddress(&pWoth, g_Woth); cudaGetSymbolAddress(&pWotl, g_Wotl);
    cudaGetSymbolAddress(&pC, g_C);     cudaGetSymbolAddress(&pA, g_A);

    cudaFuncSetAttribute(gemm_mma, cudaFuncAttributeMaxDynamicSharedMemorySize, GSMEM);
    cudaFuncSetAttribute(attn_kernel, cudaFuncAttributeMaxDynamicSharedMemorySize, ATTN_SMEM);

    // 1) split X and weights into bf16 hi/lo (weights transposed to [N,K])
    split_vec<<<4096, 256>>>(x, (__nv_bfloat16*)pXh, (__nv_bfloat16*)pXl,
                             MROWS * EMB / 4);
    tsplit<<<dim3(64, 64), dim3(32, 8)>>>(Wq, (__nv_bfloat16*)pWth, (__nv_bfloat16*)pWtl, 2048, 0);
    tsplit<<<dim3(4,  64), dim3(32, 8)>>>(Wk, (__nv_bfloat16*)pWth, (__nv_bfloat16*)pWtl, 128, 2048);
    tsplit<<<dim3(4,  64), dim3(32, 8)>>>(Wv, (__nv_bfloat16*)pWth, (__nv_bfloat16*)pWtl, 128, 2176);
    tsplit<<<dim3(64, 64), dim3(32, 8)>>>(Wo, (__nv_bfloat16*)pWoth, (__nv_bfloat16*)pWotl, 2048, 0);

    // 2) fused QKV projection: C[8192,2304] = X @ [Wq|Wk|Wv]
    gemm_mma<<<dim3(NQKV / 128, MROWS / 128), 256, GSMEM>>>(
        (const __nv_bfloat16*)pXh, (const __nv_bfloat16*)pXl,
        (const __nv_bfloat16*)pWth, (const __nv_bfloat16*)pWtl,
        (float*)pC, nullptr, NQKV);

    // 3) causal MQA flash attention -> g_A
    attn_kernel<<<dim3(TLEN / BR, NH, BSZ), 256, ATTN_SMEM>>>();

    // 4) split attention output, O-projection with fused bias
    split_vec<<<4096, 256>>>((const float*)pA, (__nv_bfloat16*)pAh, (__nv_bfloat16*)pAl,
                             MROWS * EMB / 4);
    gemm_mma<<<dim3(EMB / 128, MROWS / 128), 256, GSMEM>>>(
        (const __nv_bfloat16*)pAh, (const __nv_bfloat16*)pAl,
        (const __nv_bfloat16*)pWoth, (const __nv_bfloat16*)pWotl,
        out, bo, EMB);
}

// round 11
// speedup vs baseline: 5.6016x; 2.1543x over previous
#include <cuda_runtime.h>
#include <cuda_bf16.h>
#include <stdint.h>
#include <math.h>

#define EMB   2048
#define NH    16
#define DH    128
#define BSZ   4
#define TLEN  2048
#define MROWS (BSZ*TLEN)   // 8192
#define NQKV  2304         // 2048 (Q heads) + 128 (K) + 128 (V)
#define GK    2048         // GEMM K depth

// ---------------- scratch (static device globals; no allocations) ----------
__device__ __nv_bfloat16 g_Xh[MROWS*GK],  g_Xl[MROWS*GK];    // split x
__device__ __nv_bfloat16 g_Ch[MROWS*NQKV], g_Cl[MROWS*NQKV]; // split QKV out
__device__ __nv_bfloat16 g_Ah[MROWS*EMB], g_Al[MROWS*EMB];   // split attn out
__device__ __nv_bfloat16 g_Wth[NQKV*GK],  g_Wtl[NQKV*GK];    // [Wq|Wk|Wv]^T [N,K]
__device__ __nv_bfloat16 g_Woth[EMB*GK],  g_Wotl[EMB*GK];    // Wo^T [N,K]

// ==================== helpers ==============================================
__device__ __forceinline__ uint32_t smem_u32(const void* p) {
    uint32_t a;
    asm("{ .reg .u64 t; cvta.to.shared.u64 t, %1; cvt.u32.u64 %0, t; }"
        : "=r"(a) : "l"(p));
    return a;
}
__device__ __forceinline__ void cp_async16(uint32_t dst, const void* src) {
    asm volatile("cp.async.cg.shared.global [%0], [%1], 16;\n"
                 :: "r"(dst), "l"(src));
}
#define CP_COMMIT()  asm volatile("cp.async.commit_group;\n" ::: "memory")
#define CP_WAIT(n)   asm volatile("cp.async.wait_group %0;\n" :: "n"(n) : "memory")

__device__ __forceinline__ void ldm_x4(uint32_t& r0, uint32_t& r1,
                                       uint32_t& r2, uint32_t& r3, uint32_t a) {
    asm volatile("ldmatrix.sync.aligned.m8n8.x4.shared.b16 {%0,%1,%2,%3}, [%4];"
                 : "=r"(r0), "=r"(r1), "=r"(r2), "=r"(r3) : "r"(a));
}
__device__ __forceinline__ void ldm_x4t(uint32_t& r0, uint32_t& r1,
                                        uint32_t& r2, uint32_t& r3, uint32_t a) {
    asm volatile("ldmatrix.sync.aligned.m8n8.x4.trans.shared.b16 {%0,%1,%2,%3}, [%4];"
                 : "=r"(r0), "=r"(r1), "=r"(r2), "=r"(r3) : "r"(a));
}
__device__ __forceinline__ void mma_bf16(float* c, const uint32_t* a,
                                         uint32_t b0, uint32_t b1) {
    asm volatile(
        "mma.sync.aligned.m16n8k16.row.col.f32.bf16.bf16.f32 "
        "{%0,%1,%2,%3}, {%4,%5,%6,%7}, {%8,%9}, {%0,%1,%2,%3};"
        : "+f"(c[0]), "+f"(c[1]), "+f"(c[2]), "+f"(c[3])
        : "r"(a[0]), "r"(a[1]), "r"(a[2]), "r"(a[3]), "r"(b0), "r"(b1));
}
__device__ __forceinline__ uint32_t b2u(__nv_bfloat162 v) {
    union { __nv_bfloat162 b; uint32_t u; } cv; cv.b = v; return cv.u;
}
// store fp32 pair as hi/lo bf16x2 at element offset off
__device__ __forceinline__ void store_split(__nv_bfloat16* Ch, __nv_bfloat16* Cl,
                                            size_t off, float v0, float v1) {
    __nv_bfloat16 h0 = __float2bfloat16(v0), h1 = __float2bfloat16(v1);
    *(__nv_bfloat162*)(Ch + off) = __halves2bfloat162(h0, h1);
    *(__nv_bfloat162*)(Cl + off) = __halves2bfloat162(
        __float2bfloat16(v0 - __bfloat162float(h0)),
        __float2bfloat16(v1 - __bfloat162float(h1)));
}

// ==================== conversion kernels ===================================
__device__ __forceinline__ void split1(float v, __nv_bfloat16& h, __nv_bfloat16& l) {
    h = __float2bfloat16(v);
    l = __float2bfloat16(v - __bfloat162float(h));
}

__global__ void split_vec(const float* __restrict__ src,
                          __nv_bfloat16* __restrict__ h,
                          __nv_bfloat16* __restrict__ l, int n4) {
    int i = blockIdx.x * blockDim.x + threadIdx.x;
    int stride = gridDim.x * blockDim.x;
    __nv_bfloat162* H = (__nv_bfloat162*)h;
    __nv_bfloat162* L = (__nv_bfloat162*)l;
    for (; i < n4; i += stride) {
        float4 v = ((const float4*)src)[i];
        __nv_bfloat16 h0, l0, h1, l1, h2, l2, h3, l3;
        split1(v.x, h0, l0); split1(v.y, h1, l1);
        split1(v.z, h2, l2); split1(v.w, h3, l3);
        H[2*i]     = __halves2bfloat162(h0, h1);
        H[2*i + 1] = __halves2bfloat162(h2, h3);
        L[2*i]     = __halves2bfloat162(l0, l1);
        L[2*i + 1] = __halves2bfloat162(l2, l3);
    }
}

// transpose + split: src [2048(K)][N] fp32 -> dest [(rowOff+n)][k] bf16, ld 2048
__global__ void tsplit(const float* __restrict__ src,
                       __nv_bfloat16* __restrict__ dh,
                       __nv_bfloat16* __restrict__ dl, int N, int rowOff) {
    __shared__ float t[32][33];
    int n0 = blockIdx.x * 32, k0 = blockIdx.y * 32;
    int tx = threadIdx.x, ty = threadIdx.y;     // 32 x 8
    #pragma unroll
    for (int r = 0; r < 4; r++)
        t[ty + r*8][tx] = src[(size_t)(k0 + ty + r*8) * N + n0 + tx];
    __syncthreads();
    #pragma unroll
    for (int r = 0; r < 4; r++) {
        int n = n0 + ty + r*8, k = k0 + tx;
        float v = t[tx][ty + r*8];
        __nv_bfloat16 h, l; split1(v, h, l);
        size_t o = (size_t)(n + rowOff) * GK + k;
        dh[o] = h; dl[o] = l;
    }
}

// ==================== mma.sync split-bf16 GEMM =============================
// C[M,N] = A[M,K] * B[N,K]^T via 3-term bf16 split.
// CTA 128x128, 8 warps (2x4), warp tile 64x32, K-chunk 64, 2-stage cp.async.
// Output: either fp32 (+bias) to Cf, or split bf16 to Ch/Cl.
#define KC      64
#define LDSE    72
#define TILE_B  (128*LDSE*2)
#define STAGE_B (4*TILE_B)
#define GSMEM   (2*STAGE_B)
#define NCHUNK  (GK/KC)

__global__ __launch_bounds__(256)
void gemm_mma(const __nv_bfloat16* __restrict__ Ah, const __nv_bfloat16* __restrict__ Al,
              const __nv_bfloat16* __restrict__ Bh, const __nv_bfloat16* __restrict__ Bl,
              __nv_bfloat16* __restrict__ Ch, __nv_bfloat16* __restrict__ Cl,
              float* __restrict__ Cf, const float* __restrict__ bias, int ldc) {
    extern __shared__ char smem[];
    const uint32_t sb = smem_u32(smem);

    const int tid  = threadIdx.x;
    const int wid  = tid >> 5;
    const int lane = tid & 31;
    const int wm   = wid >> 2;
    const int wn   = wid & 3;
    const int row0 = blockIdx.y * 128;
    const int n0   = blockIdx.x * 128;

    const __nv_bfloat16* pAh = Ah + (size_t)row0 * GK;
    const __nv_bfloat16* pAl = Al + (size_t)row0 * GK;
    const __nv_bfloat16* pBh = Bh + (size_t)n0 * GK;
    const __nv_bfloat16* pBl = Bl + (size_t)n0 * GK;

    const int cr = tid >> 3;
    const int cc = tid & 7;

    float acc[4][4][4];
    #pragma unroll
    for (int i = 0; i < 4; i++)
        #pragma unroll
        for (int j = 0; j < 4; j++)
            #pragma unroll
            for (int r = 0; r < 4; r++) acc[i][j][r] = 0.0f;

    const int a_row = wm * 64 + (lane & 15);
    const int a_col = (lane >> 4) * 8;
    const int b_g   = lane >> 3;
    const int b_row = wn * 32 + ((b_g >> 1) * 8) + (lane & 7);
    const int b_col = (b_g & 1) * 8;

    auto load_stage = [&](int s, int c) {
        const uint32_t st = sb + s * STAGE_B;
        const int k0 = c * KC;
        #pragma unroll
        for (int it = 0; it < 4; ++it) {
            int r = cr + it * 32;
            uint32_t so = (uint32_t)(r * (LDSE*2) + cc * 16);
            size_t   go = (size_t)r * GK + k0 + cc * 8;
            cp_async16(st + 0*TILE_B + so, pAh + go);
            cp_async16(st + 1*TILE_B + so, pAl + go);
            cp_async16(st + 2*TILE_B + so, pBh + go);
            cp_async16(st + 3*TILE_B + so, pBl + go);
        }
        CP_COMMIT();
    };

    load_stage(0, 0);

    for (int c = 0; c < NCHUNK; ++c) {
        if (c + 1 < NCHUNK) { load_stage((c + 1) & 1, c + 1); CP_WAIT(1); }
        else                { CP_WAIT(0); }
        __syncthreads();

        const uint32_t st = sb + (c & 1) * STAGE_B;
        const uint32_t aBh = st + 0*TILE_B;
        const uint32_t aBl_= st + 1*TILE_B;
        const uint32_t bBh = st + 2*TILE_B;
        const uint32_t bBl = st + 3*TILE_B;

        #pragma unroll
        for (int ks = 0; ks < 4; ++ks) {
            uint32_t ah[4][4], al[4][4];
            #pragma unroll
            for (int mi = 0; mi < 4; ++mi) {
                uint32_t off = (uint32_t)((a_row + mi*16) * (LDSE*2)
                                          + (a_col + ks*16) * 2);
                ldm_x4(ah[mi][0], ah[mi][1], ah[mi][2], ah[mi][3], aBh + off);
                ldm_x4(al[mi][0], al[mi][1], al[mi][2], al[mi][3], aBl_ + off);
            }
            uint32_t bh[8], bl[8];
            #pragma unroll
            for (int nb = 0; nb < 2; ++nb) {
                uint32_t off = (uint32_t)((b_row + nb*16) * (LDSE*2)
                                          + (b_col + ks*16) * 2);
                ldm_x4(bh[nb*4+0], bh[nb*4+1], bh[nb*4+2], bh[nb*4+3], bBh + off);
                ldm_x4(bl[nb*4+0], bl[nb*4+1], bl[nb*4+2], bl[nb*4+3], bBl + off);
            }
            #pragma unroll
            for (int mi = 0; mi < 4; ++mi) {
                #pragma unroll
                for (int ni = 0; ni < 4; ++ni) {
                    uint32_t b0h = bh[ni*2], b1h = bh[ni*2+1];
                    uint32_t b0l = bl[ni*2], b1l = bl[ni*2+1];
                    mma_bf16(acc[mi][ni], ah[mi], b0h, b1h);
                    mma_bf16(acc[mi][ni], ah[mi], b0l, b1l);
                    mma_bf16(acc[mi][ni], al[mi], b0h, b1h);
                }
            }
        }
        __syncthreads();
    }

    const int er = lane >> 2;
    const int ec = (lane & 3) * 2;
    #pragma unroll
    for (int mi = 0; mi < 4; ++mi) {
        #pragma unroll
        for (int ni = 0; ni < 4; ++ni) {
            int gr = row0 + wm*64 + mi*16 + er;
            int gc = n0 + wn*32 + ni*8 + ec;
            if (Cf) {
                float bx = 0.f, by = 0.f;
                if (bias) { bx = bias[gc]; by = bias[gc + 1]; }
                float2 v0 = make_float2(acc[mi][ni][0] + bx, acc[mi][ni][1] + by);
                float2 v1 = make_float2(acc[mi][ni][2] + bx, acc[mi][ni][3] + by);
                *(float2*)&Cf[(size_t)gr * ldc + gc]       = v0;
                *(float2*)&Cf[(size_t)(gr + 8) * ldc + gc] = v1;
            } else {
                store_split(Ch, Cl, (size_t)gr * ldc + gc,
                            acc[mi][ni][0], acc[mi][ni][1]);
                store_split(Ch, Cl, (size_t)(gr + 8) * ldc + gc,
                            acc[mi][ni][2], acc[mi][ni][3]);
            }
        }
    }
}

// ==================== tensor-core causal MQA flash attention ===============
// Per CTA: (b, h, 128-row Q tile). 8 warps, warp = 16 Q rows.
// KV tiles of 64 keys, 2-term bf16 split on Q,K,P,V (3-term products).
#define LDA   136                 // elems per smem row (128 + 8 pad)
#define ROWB  (LDA*2)             // 272 bytes
#define QH_OFF 0
#define QL_OFF (128*ROWB)         // 34816
#define KH_OFF (2*128*ROWB)       // 69632
#define KLSTEP (64*ROWB)          // 17408 (Kl = Kh + 1 step, Vh + 2, Vl + 3)
#define VH_OFF (KH_OFF + 2*KLSTEP)
#define ATT_SMEM (KH_OFF + 4*KLSTEP)   // 139264

__global__ __launch_bounds__(256, 1)
void attn_mma() {
    extern __shared__ char smc[];
    const uint32_t sb = smem_u32(smc);
    const int tid = threadIdx.x, w = tid >> 5, lane = tid & 31;
    const int qt = blockIdx.x, h = blockIdx.y, b = blockIdx.z;
    const int q0 = qt * 128;
    const size_t qrow = (size_t)(b * TLEN + q0);

    // ---- async-load Q tile hi/lo (128 rows x 128 cols bf16 each) ----
    #pragma unroll
    for (int it = 0; it < 16; ++it) {
        int f = tid + it * 256;           // 0..4095
        int arr = f >> 11;                // 0=hi 1=lo
        int r   = (f >> 4) & 127;
        int c   = f & 15;
        const __nv_bfloat16* src = (arr ? g_Cl : g_Ch)
            + (qrow + r) * NQKV + h * DH + c * 8;
        cp_async16(sb + arr * QL_OFF + r * ROWB + c * 16, src);
    }
    CP_COMMIT();

    const int bg = lane >> 3;
    const uint32_t qa = sb + (16*w + (lane & 15)) * ROWB + ((lane >> 4) * 8) * 2;
    const uint32_t ka = sb + KH_OFF + (((bg >> 1) * 8) + (lane & 7)) * ROWB
                        + ((bg & 1) * 8) * 2;
    const uint32_t va = sb + VH_OFF + (((bg & 1) * 8) + (lane & 7)) * ROWB
                        + ((bg >> 1) * 8) * 2;

    float O[16][4];
    #pragma unroll
    for (int i = 0; i < 16; i++) { O[i][0]=0.f; O[i][1]=0.f; O[i][2]=0.f; O[i][3]=0.f; }
    float m0 = -1e30f, m1 = -1e30f, l0 = 0.f, l1 = 0.f;
    const float scale = 0.08838834764831845f;   // 1/sqrt(128)

    const int ntile = 2 * qt + 2;
    for (int jt = 0; jt < ntile; ++jt) {
        if (jt) __syncthreads();                 // smem reads of prev tile done

        // ---- async-load K/V tiles hi/lo (64 x 128 each) ----
        const size_t krow = (size_t)(b * TLEN + jt * 64);
        #pragma unroll
        for (int it = 0; it < 16; ++it) {
            int f = tid + it * 256;
            int arr = f >> 10;                   // 0 Kh,1 Kl,2 Vh,3 Vl
            int r   = (f >> 4) & 63;
            int c   = f & 15;
            const __nv_bfloat16* src = ((arr & 1) ? g_Cl : g_Ch)
                + (krow + r) * NQKV + ((arr < 2) ? 2048 : 2176) + c * 8;
            cp_async16(sb + KH_OFF + arr * KLSTEP + r * ROWB + c * 16, src);
        }
        CP_COMMIT();
        CP_WAIT(0);
        __syncthreads();

        // ---- S = Q K^T (3-term split), warp rows 16w..16w+15, cols 0..63 ----
        float S[8][4];
        #pragma unroll
        for (int i = 0; i < 8; i++) { S[i][0]=0.f; S[i][1]=0.f; S[i][2]=0.f; S[i][3]=0.f; }

        #pragma unroll
        for (int ks = 0; ks < 8; ++ks) {
            uint32_t ah[4], al[4];
            ldm_x4(ah[0], ah[1], ah[2], ah[3], qa + ks*32);
            ldm_x4(al[0], al[1], al[2], al[3], qa + QL_OFF + ks*32);
            #pragma unroll
            for (int nn = 0; nn < 4; ++nn) {
                uint32_t kh[4], kl[4];
                ldm_x4(kh[0], kh[1], kh[2], kh[3],
                       ka + nn*(16*ROWB) + ks*32);
                ldm_x4(kl[0], kl[1], kl[2], kl[3],
                       ka + KLSTEP + nn*(16*ROWB) + ks*32);
                mma_bf16(S[2*nn],   ah, kh[0], kh[1]);
                mma_bf16(S[2*nn],   ah, kl[0], kl[1]);
                mma_bf16(S[2*nn],   al, kh[0], kh[1]);
                mma_bf16(S[2*nn+1], ah, kh[2], kh[3]);
                mma_bf16(S[2*nn+1], ah, kl[2], kl[3]);
                mma_bf16(S[2*nn+1], al, kh[2], kh[3]);
            }
        }

        // ---- scale + causal mask ----
        const int gr0 = q0 + 16*w + (lane >> 2);
        const int cb  = jt*64 + 2*(lane & 3);
        #pragma unroll
        for (int nt = 0; nt < 8; ++nt) {
            S[nt][0] *= scale; S[nt][1] *= scale;
            S[nt][2] *= scale; S[nt][3] *= scale;
        }
        if (jt >= 2*qt) {
            #pragma unroll
            for (int nt = 0; nt < 8; ++nt) {
                int gk = cb + 8*nt;
                if (gk     > gr0)     S[nt][0] = -1e30f;
                if (gk + 1 > gr0)     S[nt][1] = -1e30f;
                if (gk     > gr0 + 8) S[nt][2] = -1e30f;
                if (gk + 1 > gr0 + 8) S[nt][3] = -1e30f;
            }
        }

        // ---- online softmax ----
        float rm0 = -1e30f, rm1 = -1e30f;
        #pragma unroll
        for (int nt = 0; nt < 8; ++nt) {
            rm0 = fmaxf(rm0, fmaxf(S[nt][0], S[nt][1]));
            rm1 = fmaxf(rm1, fmaxf(S[nt][2], S[nt][3]));
        }
        rm0 = fmaxf(rm0, __shfl_xor_sync(0xffffffffu, rm0, 1));
        rm0 = fmaxf(rm0, __shfl_xor_sync(0xffffffffu, rm0, 2));
        rm1 = fmaxf(rm1, __shfl_xor_sync(0xffffffffu, rm1, 1));
        rm1 = fmaxf(rm1, __shfl_xor_sync(0xffffffffu, rm1, 2));
        float mn0 = fmaxf(m0, rm0), mn1 = fmaxf(m1, rm1);
        float a0 = __expf(m0 - mn0), a1 = __expf(m1 - mn1);
        m0 = mn0; m1 = mn1;

        uint32_t phi[4][4], plo[4][4];
        float rs0 = 0.f, rs1 = 0.f;
        #pragma unroll
        for (int nt = 0; nt < 8; ++nt) {
            float p0 = __expf(S[nt][0] - mn0), p1 = __expf(S[nt][1] - mn0);
            float p2 = __expf(S[nt][2] - mn1), p3 = __expf(S[nt][3] - mn1);
            rs0 += p0 + p1;  rs1 += p2 + p3;
            __nv_bfloat16 h0 = __float2bfloat16(p0), h1 = __float2bfloat16(p1);
            __nv_bfloat16 h2 = __float2bfloat16(p2), h3 = __float2bfloat16(p3);
            int ki = nt >> 1, sl = (nt & 1) * 2;
            phi[ki][sl+0] = b2u(__halves2bfloat162(h0, h1));
            phi[ki][sl+1] = b2u(__halves2bfloat162(h2, h3));
            plo[ki][sl+0] = b2u(__halves2bfloat162(
                __float2bfloat16(p0 - __bfloat162float(h0)),
                __float2bfloat16(p1 - __bfloat162float(h1))));
            plo[ki][sl+1] = b2u(__halves2bfloat162(
                __float2bfloat16(p2 - __bfloat162float(h2)),
                __float2bfloat16(p3 - __bfloat162float(h3))));
        }
        rs0 += __shfl_xor_sync(0xffffffffu, rs0, 1);
        rs0 += __shfl_xor_sync(0xffffffffu, rs0, 2);
        rs1 += __shfl_xor_sync(0xffffffffu, rs1, 1);
        rs1 += __shfl_xor_sync(0xffffffffu, rs1, 2);
        l0 = l0 * a0 + rs0;  l1 = l1 * a1 + rs1;

        #pragma unroll
        for (int ni = 0; ni < 16; ++ni) {
            O[ni][0] *= a0; O[ni][1] *= a0; O[ni][2] *= a1; O[ni][3] *= a1;
        }

        // ---- O += P V (3-term split), V^T via ldmatrix.trans ----
        #pragma unroll
        for (int ki = 0; ki < 4; ++ki) {
            #pragma unroll
            for (int nb = 0; nb < 8; ++nb) {
                uint32_t vh[4], vl[4];
                ldm_x4t(vh[0], vh[1], vh[2], vh[3],
                        va + ki*(16*ROWB) + nb*32);
                ldm_x4t(vl[0], vl[1], vl[2], vl[3],
                        va + KLSTEP + ki*(16*ROWB) + nb*32);
                mma_bf16(O[2*nb],   phi[ki], vh[0], vh[1]);
                mma_bf16(O[2*nb],   phi[ki], vl[0], vl[1]);
                mma_bf16(O[2*nb],   plo[ki], vh[0], vh[1]);
                mma_bf16(O[2*nb+1], phi[ki], vh[2], vh[3]);
                mma_bf16(O[2*nb+1], phi[ki], vl[2], vl[3]);
                mma_bf16(O[2*nb+1], plo[ki], vh[2], vh[3]);
            }
        }
    }

    // ---- epilogue: normalize, split to bf16 hi/lo, store ----
    float il0 = 1.0f / l0, il1 = 1.0f / l1;
    size_t r0 = qrow + 16*w + (lane >> 2);
    int colb = h * DH + 2 * (lane & 3);
    #pragma unroll
    for (int ni = 0; ni < 16; ++ni) {
        int col = colb + 8 * ni;
        store_split(g_Ah, g_Al, r0 * EMB + col,
                    O[ni][0] * il0, O[ni][1] * il0);
        store_split(g_Ah, g_Al, (r0 + 8) * EMB + col,
                    O[ni][2] * il1, O[ni][3] * il1);
    }
}

// ==================== launch ===============================================
extern "C" void kernel_launch(void* const* d_in, const int* in_sizes, int n_in,
                              void* d_out, int out_size) {
    const float* x  = (const float*)d_in[0];
    const float* Wq = (const float*)d_in[1];
    const float* Wk = (const float*)d_in[2];
    const float* Wv = (const float*)d_in[3];
    const float* Wo = (const float*)d_in[4];
    const float* bo = (const float*)d_in[5];
    float* out = (float*)d_out;
    (void)in_sizes; (void)n_in; (void)out_size;

    void *pXh, *pXl, *pAh, *pAl, *pWth, *pWtl, *pWoth, *pWotl, *pCh, *pCl;
    cudaGetSymbolAddress(&pXh, g_Xh);     cudaGetSymbolAddress(&pXl, g_Xl);
    cudaGetSymbolAddress(&pAh, g_Ah);     cudaGetSymbolAddress(&pAl, g_Al);
    cudaGetSymbolAddress(&pWth, g_Wth);   cudaGetSymbolAddress(&pWtl, g_Wtl);
    cudaGetSymbolAddress(&pWoth, g_Woth); cudaGetSymbolAddress(&pWotl, g_Wotl);
    cudaGetSymbolAddress(&pCh, g_Ch);     cudaGetSymbolAddress(&pCl, g_Cl);

    cudaFuncSetAttribute(gemm_mma, cudaFuncAttributeMaxDynamicSharedMemorySize, GSMEM);
    cudaFuncSetAttribute(attn_mma, cudaFuncAttributeMaxDynamicSharedMemorySize, ATT_SMEM);

    // 1) split x; transpose+split weights
    split_vec<<<4096, 256>>>(x, (__nv_bfloat16*)pXh, (__nv_bfloat16*)pXl,
                             MROWS * EMB / 4);
    tsplit<<<dim3(64, 64), dim3(32, 8)>>>(Wq, (__nv_bfloat16*)pWth, (__nv_bfloat16*)pWtl, 2048, 0);
    tsplit<<<dim3(4,  64), dim3(32, 8)>>>(Wk, (__nv_bfloat16*)pWth, (__nv_bfloat16*)pWtl, 128, 2048);
    tsplit<<<dim3(4,  64), dim3(32, 8)>>>(Wv, (__nv_bfloat16*)pWth, (__nv_bfloat16*)pWtl, 128, 2176);
    tsplit<<<dim3(64, 64), dim3(32, 8)>>>(Wo, (__nv_bfloat16*)pWoth, (__nv_bfloat16*)pWotl, 2048, 0);

    // 2) fused QKV projection -> split bf16 g_Ch/g_Cl
    gemm_mma<<<dim3(NQKV / 128, MROWS / 128), 256, GSMEM>>>(
        (const __nv_bfloat16*)pXh, (const __nv_bfloat16*)pXl,
        (const __nv_bfloat16*)pWth, (const __nv_bfloat16*)pWtl,
        (__nv_bfloat16*)pCh, (__nv_bfloat16*)pCl, nullptr, nullptr, NQKV);

    // 3) tensor-core causal MQA flash attention -> split bf16 g_Ah/g_Al
    attn_mma<<<dim3(TLEN / 128, NH, BSZ), 256, ATT_SMEM>>>();

    // 4) O-projection with fused bias -> fp32 out
    gemm_mma<<<dim3(EMB / 128, MROWS / 128), 256, GSMEM>>>(
        (const __nv_bfloat16*)pAh, (const __nv_bfloat16*)pAl,
        (const __nv_bfloat16*)pWoth, (const __nv_bfloat16*)pWotl,
        nullptr, nullptr, out, bo, EMB);
}

// round 12
// speedup vs baseline: 5.7543x; 1.0273x over previous
#include <cuda_runtime.h>
#include <cuda_bf16.h>
#include <stdint.h>
#include <math.h>

#define EMB   2048
#define NH    16
#define DH    128
#define BSZ   4
#define TLEN  2048
#define MROWS (BSZ*TLEN)   // 8192
#define NQKV  2304         // 2048 (Q heads) + 128 (K) + 128 (V)
#define GK    2048         // GEMM K depth

// ---------------- scratch (static device globals; no allocations) ----------
__device__ __nv_bfloat16 g_Xh[MROWS*GK],  g_Xl[MROWS*GK];    // split x
__device__ __nv_bfloat16 g_Ch[MROWS*NQKV], g_Cl[MROWS*NQKV]; // split QKV out
__device__ __nv_bfloat16 g_Ah[MROWS*EMB], g_Al[MROWS*EMB];   // split attn out
__device__ __nv_bfloat16 g_Wth[NQKV*GK],  g_Wtl[NQKV*GK];    // [Wq|Wk|Wv]^T [N,K]
__device__ __nv_bfloat16 g_Woth[EMB*GK],  g_Wotl[EMB*GK];    // Wo^T [N,K]

// ==================== helpers ==============================================
__device__ __forceinline__ uint32_t smem_u32(const void* p) {
    uint32_t a;
    asm("{ .reg .u64 t; cvta.to.shared.u64 t, %1; cvt.u32.u64 %0, t; }"
        : "=r"(a) : "l"(p));
    return a;
}
__device__ __forceinline__ void cp_async16(uint32_t dst, const void* src) {
    asm volatile("cp.async.cg.shared.global [%0], [%1], 16;\n"
                 :: "r"(dst), "l"(src));
}
#define CP_COMMIT()  asm volatile("cp.async.commit_group;\n" ::: "memory")
#define CP_WAIT(n)   asm volatile("cp.async.wait_group %0;\n" :: "n"(n) : "memory")

__device__ __forceinline__ void ldm_x4(uint32_t& r0, uint32_t& r1,
                                       uint32_t& r2, uint32_t& r3, uint32_t a) {
    asm volatile("ldmatrix.sync.aligned.m8n8.x4.shared.b16 {%0,%1,%2,%3}, [%4];"
                 : "=r"(r0), "=r"(r1), "=r"(r2), "=r"(r3) : "r"(a));
}
__device__ __forceinline__ void ldm_x4t(uint32_t& r0, uint32_t& r1,
                                        uint32_t& r2, uint32_t& r3, uint32_t a) {
    asm volatile("ldmatrix.sync.aligned.m8n8.x4.trans.shared.b16 {%0,%1,%2,%3}, [%4];"
                 : "=r"(r0), "=r"(r1), "=r"(r2), "=r"(r3) : "r"(a));
}
__device__ __forceinline__ void mma_bf16(float* c, const uint32_t* a,
                                         uint32_t b0, uint32_t b1) {
    asm volatile(
        "mma.sync.aligned.m16n8k16.row.col.f32.bf16.bf16.f32 "
        "{%0,%1,%2,%3}, {%4,%5,%6,%7}, {%8,%9}, {%0,%1,%2,%3};"
        : "+f"(c[0]), "+f"(c[1]), "+f"(c[2]), "+f"(c[3])
        : "r"(a[0]), "r"(a[1]), "r"(a[2]), "r"(a[3]), "r"(b0), "r"(b1));
}
__device__ __forceinline__ uint32_t b2u(__nv_bfloat162 v) {
    union { __nv_bfloat162 b; uint32_t u; } cv; cv.b = v; return cv.u;
}
__device__ __forceinline__ void store_split(__nv_bfloat16* Ch, __nv_bfloat16* Cl,
                                            size_t off, float v0, float v1) {
    __nv_bfloat16 h0 = __float2bfloat16(v0), h1 = __float2bfloat16(v1);
    *(__nv_bfloat162*)(Ch + off) = __halves2bfloat162(h0, h1);
    *(__nv_bfloat162*)(Cl + off) = __halves2bfloat162(
        __float2bfloat16(v0 - __bfloat162float(h0)),
        __float2bfloat16(v1 - __bfloat162float(h1)));
}

// ==================== conversion kernels ===================================
__device__ __forceinline__ void split1(float v, __nv_bfloat16& h, __nv_bfloat16& l) {
    h = __float2bfloat16(v);
    l = __float2bfloat16(v - __bfloat162float(h));
}

__global__ void split_vec(const float* __restrict__ src,
                          __nv_bfloat16* __restrict__ h,
                          __nv_bfloat16* __restrict__ l, int n4) {
    int i = blockIdx.x * blockDim.x + threadIdx.x;
    int stride = gridDim.x * blockDim.x;
    __nv_bfloat162* H = (__nv_bfloat162*)h;
    __nv_bfloat162* L = (__nv_bfloat162*)l;
    for (; i < n4; i += stride) {
        float4 v = ((const float4*)src)[i];
        __nv_bfloat16 h0, l0, h1, l1, h2, l2, h3, l3;
        split1(v.x, h0, l0); split1(v.y, h1, l1);
        split1(v.z, h2, l2); split1(v.w, h3, l3);
        H[2*i]     = __halves2bfloat162(h0, h1);
        H[2*i + 1] = __halves2bfloat162(h2, h3);
        L[2*i]     = __halves2bfloat162(l0, l1);
        L[2*i + 1] = __halves2bfloat162(l2, l3);
    }
}

__global__ void tsplit(const float* __restrict__ src,
                       __nv_bfloat16* __restrict__ dh,
                       __nv_bfloat16* __restrict__ dl, int N, int rowOff) {
    __shared__ float t[32][33];
    int n0 = blockIdx.x * 32, k0 = blockIdx.y * 32;
    int tx = threadIdx.x, ty = threadIdx.y;     // 32 x 8
    #pragma unroll
    for (int r = 0; r < 4; r++)
        t[ty + r*8][tx] = src[(size_t)(k0 + ty + r*8) * N + n0 + tx];
    __syncthreads();
    #pragma unroll
    for (int r = 0; r < 4; r++) {
        int n = n0 + ty + r*8, k = k0 + tx;
        float v = t[tx][ty + r*8];
        __nv_bfloat16 h, l; split1(v, h, l);
        size_t o = (size_t)(n + rowOff) * GK + k;
        dh[o] = h; dl[o] = l;
    }
}

// ==================== mma.sync split-bf16 GEMM =============================
// C[M,N] = A[M,K] * B[N,K]^T via 3-term bf16 split.
// CTA 256x128, 8 warps (4 in M x 2 in N), warp tile 64x64.
// K-chunk 64, 2-stage cp.async, one __syncthreads per chunk.
#define KC      64
#define LDSE    72                       // bf16 elems per smem row (64+8 pad)
#define ROW2    (LDSE*2)                 // 144 B
// stage rows: [0,256) A-hi | [256,512) A-lo | [512,640) B-hi | [640,768) B-lo
#define AL_OFF  (256*ROW2)
#define BH_OFF  (512*ROW2)
#define BL_OFF  (640*ROW2)
#define STAGE_B (768*ROW2)               // 110592 B
#define GSMEM   (2*STAGE_B)              // 221184 B
#define NCHUNK  (GK/KC)                  // 32

__global__ __launch_bounds__(256, 1)
void gemm_mma(const __nv_bfloat16* __restrict__ Ah, const __nv_bfloat16* __restrict__ Al,
              const __nv_bfloat16* __restrict__ Bh, const __nv_bfloat16* __restrict__ Bl,
              __nv_bfloat16* __restrict__ Ch, __nv_bfloat16* __restrict__ Cl,
              float* __restrict__ Cf, const float* __restrict__ bias, int ldc) {
    extern __shared__ char smem[];
    const uint32_t sb = smem_u32(smem);

    const int tid  = threadIdx.x;
    const int wid  = tid >> 5;
    const int lane = tid & 31;
    const int wm   = wid & 3;            // 0..3 : 64-row group
    const int wn   = wid >> 2;           // 0..1 : 64-col group
    const int row0 = blockIdx.y * 256;
    const int n0   = blockIdx.x * 128;

    const __nv_bfloat16* pAh = Ah + (size_t)row0 * GK;
    const __nv_bfloat16* pAl = Al + (size_t)row0 * GK;
    const __nv_bfloat16* pBh = Bh + (size_t)n0 * GK;
    const __nv_bfloat16* pBl = Bl + (size_t)n0 * GK;

    float acc[4][8][4];
    #pragma unroll
    for (int i = 0; i < 4; i++)
        #pragma unroll
        for (int j = 0; j < 8; j++) {
            acc[i][j][0] = 0.f; acc[i][j][1] = 0.f;
            acc[i][j][2] = 0.f; acc[i][j][3] = 0.f;
        }

    const int a_row = wm * 64 + (lane & 15);
    const int a_col = (lane >> 4) * 8;
    const int b_g   = lane >> 3;
    const int b_row = wn * 64 + ((b_g >> 1) * 8) + (lane & 7);
    const int b_col = (b_g & 1) * 8;

    // cp.async: 6144 16B chunks per stage, 24 per thread
    auto load_stage = [&](int s, int c) {
        const uint32_t st = sb + s * STAGE_B;
        const int k0 = c * KC;
        #pragma unroll
        for (int it = 0; it < 24; ++it) {
            int f = tid + it * 256;          // 0..6143
            int r = f >> 3;                  // smem row 0..767
            int c16 = f & 7;
            uint32_t so = (uint32_t)(r * ROW2 + c16 * 16);
            const __nv_bfloat16* src;
            if (r < 256)      src = pAh + (size_t)r * GK + k0 + c16 * 8;
            else if (r < 512) src = pAl + (size_t)(r - 256) * GK + k0 + c16 * 8;
            else if (r < 640) src = pBh + (size_t)(r - 512) * GK + k0 + c16 * 8;
            else              src = pBl + (size_t)(r - 640) * GK + k0 + c16 * 8;
            cp_async16(st + so, src);
        }
        CP_COMMIT();
    };

    load_stage(0, 0);

    for (int c = 0; c < NCHUNK; ++c) {
        CP_WAIT(0);
        __syncthreads();
        if (c + 1 < NCHUNK) load_stage((c + 1) & 1, c + 1);

        const uint32_t st = sb + (c & 1) * STAGE_B;

        #pragma unroll
        for (int ks = 0; ks < 4; ++ks) {
            uint32_t ah[4][4], al[4][4];
            #pragma unroll
            for (int mi = 0; mi < 4; ++mi) {
                uint32_t off = (uint32_t)((a_row + mi*16) * ROW2
                                          + (a_col + ks*16) * 2);
                ldm_x4(ah[mi][0], ah[mi][1], ah[mi][2], ah[mi][3], st + off);
                ldm_x4(al[mi][0], al[mi][1], al[mi][2], al[mi][3],
                       st + AL_OFF + off);
            }
            uint32_t bh[16], bl[16];
            #pragma unroll
            for (int nb = 0; nb < 4; ++nb) {
                uint32_t off = (uint32_t)((b_row + nb*16) * ROW2
                                          + (b_col + ks*16) * 2);
                ldm_x4(bh[nb*4+0], bh[nb*4+1], bh[nb*4+2], bh[nb*4+3],
                       st + BH_OFF + off);
                ldm_x4(bl[nb*4+0], bl[nb*4+1], bl[nb*4+2], bl[nb*4+3],
                       st + BL_OFF + off);
            }
            #pragma unroll
            for (int mi = 0; mi < 4; ++mi) {
                #pragma unroll
                for (int ni = 0; ni < 8; ++ni) {
                    uint32_t b0h = bh[ni*2], b1h = bh[ni*2+1];
                    uint32_t b0l = bl[ni*2], b1l = bl[ni*2+1];
                    mma_bf16(acc[mi][ni], ah[mi], b0h, b1h);
                    mma_bf16(acc[mi][ni], ah[mi], b0l, b1l);
                    mma_bf16(acc[mi][ni], al[mi], b0h, b1h);
                }
            }
        }
    }

    const int er = lane >> 2;
    const int ec = (lane & 3) * 2;
    #pragma unroll
    for (int mi = 0; mi < 4; ++mi) {
        #pragma unroll
        for (int ni = 0; ni < 8; ++ni) {
            int gr = row0 + wm*64 + mi*16 + er;
            int gc = n0 + wn*64 + ni*8 + ec;
            if (Cf) {
                float bx = 0.f, by = 0.f;
                if (bias) { bx = bias[gc]; by = bias[gc + 1]; }
                float2 v0 = make_float2(acc[mi][ni][0] + bx, acc[mi][ni][1] + by);
                float2 v1 = make_float2(acc[mi][ni][2] + bx, acc[mi][ni][3] + by);
                *(float2*)&Cf[(size_t)gr * ldc + gc]       = v0;
                *(float2*)&Cf[(size_t)(gr + 8) * ldc + gc] = v1;
            } else {
                store_split(Ch, Cl, (size_t)gr * ldc + gc,
                            acc[mi][ni][0], acc[mi][ni][1]);
                store_split(Ch, Cl, (size_t)(gr + 8) * ldc + gc,
                            acc[mi][ni][2], acc[mi][ni][3]);
            }
        }
    }
}

// ==================== tensor-core causal MQA flash attention ===============
// Per CTA: (b, h, 128-row Q tile). 8 warps x 16 Q rows. KV tiles of 64 keys,
// double-buffered. 2-term bf16 split on Q,K,P,V (3-term products).
#define LDA     136
#define ROWB    (LDA*2)                  // 272 B
#define QL_OFF  (128*ROWB)
#define KV0     (2*128*ROWB)             // KV stages base
#define KVSTAGE (256*ROWB)               // Kh|Kl|Vh|Vl, 64 rows each
#define AKL     (64*ROWB)
#define AVH     (128*ROWB)
#define AVL     (192*ROWB)
#define ATT_SMEM (KV0 + 2*KVSTAGE)       // 208896 B

__global__ __launch_bounds__(256, 1)
void attn_mma() {
    extern __shared__ char smc[];
    const uint32_t sb = smem_u32(smc);
    const int tid = threadIdx.x, w = tid >> 5, lane = tid & 31;
    const int qt = blockIdx.x, h = blockIdx.y, b = blockIdx.z;
    const int q0 = qt * 128;
    const size_t qrow = (size_t)(b * TLEN + q0);

    auto load_kv = [&](int jt, int s) {
        const size_t krow = (size_t)(b * TLEN + jt * 64);
        const uint32_t base = sb + KV0 + s * KVSTAGE;
        #pragma unroll
        for (int it = 0; it < 16; ++it) {
            int f = tid + it * 256;
            int arr = f >> 10;               // 0 Kh,1 Kl,2 Vh,3 Vl
            int r   = (f >> 4) & 63;
            int c   = f & 15;
            const __nv_bfloat16* src = ((arr & 1) ? g_Cl : g_Ch)
                + (krow + r) * NQKV + ((arr < 2) ? 2048 : 2176) + c * 8;
            cp_async16(base + arr * AKL + r * ROWB + c * 16, src);
        }
        CP_COMMIT();
    };

    // ---- prefetch Q tile + first KV tile ----
    #pragma unroll
    for (int it = 0; it < 16; ++it) {
        int f = tid + it * 256;              // 0..4095
        int arr = f >> 11;                   // 0=hi 1=lo
        int r   = (f >> 4) & 127;
        int c   = f & 15;
        const __nv_bfloat16* src = (arr ? g_Cl : g_Ch)
            + (qrow + r) * NQKV + h * DH + c * 8;
        cp_async16(sb + arr * QL_OFF + r * ROWB + c * 16, src);
    }
    load_kv(0, 0);   // commits Q + KV0 together

    const int bg = lane >> 3;
    const uint32_t qa = sb + (16*w + (lane & 15)) * ROWB + ((lane >> 4) * 8) * 2;
    const uint32_t kvb = sb + KV0;
    const uint32_t koff = (((bg >> 1) * 8) + (lane & 7)) * ROWB + ((bg & 1) * 8) * 2;
    const uint32_t voff = (((bg & 1) * 8) + (lane & 7)) * ROWB + ((bg >> 1) * 8) * 2;

    float O[16][4];
    #pragma unroll
    for (int i = 0; i < 16; i++) { O[i][0]=0.f; O[i][1]=0.f; O[i][2]=0.f; O[i][3]=0.f; }
    float m0 = -1e30f, m1 = -1e30f, l0 = 0.f, l1 = 0.f;
    const float scale = 0.08838834764831845f;   // 1/sqrt(128)

    const int ntile = 2 * qt + 2;
    for (int jt = 0; jt < ntile; ++jt) {
        CP_WAIT(0);
        __syncthreads();
        if (jt + 1 < ntile) load_kv(jt + 1, (jt + 1) & 1);

        const uint32_t st = kvb + (jt & 1) * KVSTAGE;
        const uint32_t ka = st + koff;
        const uint32_t va = st + AVH + voff;

        // ---- S = Q K^T (3-term split) ----
        float S[8][4];
        #pragma unroll
        for (int i = 0; i < 8; i++) { S[i][0]=0.f; S[i][1]=0.f; S[i][2]=0.f; S[i][3]=0.f; }

        #pragma unroll
        for (int ks = 0; ks < 8; ++ks) {
            uint32_t ah[4], al[4];
            ldm_x4(ah[0], ah[1], ah[2], ah[3], qa + ks*32);
            ldm_x4(al[0], al[1], al[2], al[3], qa + QL_OFF + ks*32);
            #pragma unroll
            for (int nn = 0; nn < 4; ++nn) {
                uint32_t kh[4], kl[4];
                ldm_x4(kh[0], kh[1], kh[2], kh[3],
                       ka + nn*(16*ROWB) + ks*32);
                ldm_x4(kl[0], kl[1], kl[2], kl[3],
                       ka + AKL + nn*(16*ROWB) + ks*32);
                mma_bf16(S[2*nn],   ah, kh[0], kh[1]);
                mma_bf16(S[2*nn],   ah, kl[0], kl[1]);
                mma_bf16(S[2*nn],   al, kh[0], kh[1]);
                mma_bf16(S[2*nn+1], ah, kh[2], kh[3]);
                mma_bf16(S[2*nn+1], ah, kl[2], kl[3]);
                mma_bf16(S[2*nn+1], al, kh[2], kh[3]);
            }
        }

        // ---- scale + causal mask ----
        const int gr0 = q0 + 16*w + (lane >> 2);
        const int cb  = jt*64 + 2*(lane & 3);
        #pragma unroll
        for (int nt = 0; nt < 8; ++nt) {
            S[nt][0] *= scale; S[nt][1] *= scale;
            S[nt][2] *= scale; S[nt][3] *= scale;
        }
        if (jt >= 2*qt) {
            #pragma unroll
            for (int nt = 0; nt < 8; ++nt) {
                int gk = cb + 8*nt;
                if (gk     > gr0)     S[nt][0] = -1e30f;
                if (gk + 1 > gr0)     S[nt][1] = -1e30f;
                if (gk     > gr0 + 8) S[nt][2] = -1e30f;
                if (gk + 1 > gr0 + 8) S[nt][3] = -1e30f;
            }
        }

        // ---- online softmax ----
        float rm0 = -1e30f, rm1 = -1e30f;
        #pragma unroll
        for (int nt = 0; nt < 8; ++nt) {
            rm0 = fmaxf(rm0, fmaxf(S[nt][0], S[nt][1]));
            rm1 = fmaxf(rm1, fmaxf(S[nt][2], S[nt][3]));
        }
        rm0 = fmaxf(rm0, __shfl_xor_sync(0xffffffffu, rm0, 1));
        rm0 = fmaxf(rm0, __shfl_xor_sync(0xffffffffu, rm0, 2));
        rm1 = fmaxf(rm1, __shfl_xor_sync(0xffffffffu, rm1, 1));
        rm1 = fmaxf(rm1, __shfl_xor_sync(0xffffffffu, rm1, 2));
        float mn0 = fmaxf(m0, rm0), mn1 = fmaxf(m1, rm1);
        float a0 = __expf(m0 - mn0), a1 = __expf(m1 - mn1);
        m0 = mn0; m1 = mn1;

        uint32_t phi[4][4], plo[4][4];
        float rs0 = 0.f, rs1 = 0.f;
        #pragma unroll
        for (int nt = 0; nt < 8; ++nt) {
            float p0 = __expf(S[nt][0] - mn0), p1 = __expf(S[nt][1] - mn0);
            float p2 = __expf(S[nt][2] - mn1), p3 = __expf(S[nt][3] - mn1);
            rs0 += p0 + p1;  rs1 += p2 + p3;
            __nv_bfloat16 h0 = __float2bfloat16(p0), h1 = __float2bfloat16(p1);
            __nv_bfloat16 h2 = __float2bfloat16(p2), h3 = __float2bfloat16(p3);
            int ki = nt >> 1, sl = (nt & 1) * 2;
            phi[ki][sl+0] = b2u(__halves2bfloat162(h0, h1));
            phi[ki][sl+1] = b2u(__halves2bfloat162(h2, h3));
            plo[ki][sl+0] = b2u(__halves2bfloat162(
                __float2bfloat16(p0 - __bfloat162float(h0)),
                __float2bfloat16(p1 - __bfloat162float(h1))));
            plo[ki][sl+1] = b2u(__halves2bfloat162(
                __float2bfloat16(p2 - __bfloat162float(h2)),
                __float2bfloat16(p3 - __bfloat162float(h3))));
        }
        rs0 += __shfl_xor_sync(0xffffffffu, rs0, 1);
        rs0 += __shfl_xor_sync(0xffffffffu, rs0, 2);
        rs1 += __shfl_xor_sync(0xffffffffu, rs1, 1);
        rs1 += __shfl_xor_sync(0xffffffffu, rs1, 2);
        l0 = l0 * a0 + rs0;  l1 = l1 * a1 + rs1;

        #pragma unroll
        for (int ni = 0; ni < 16; ++ni) {
            O[ni][0] *= a0; O[ni][1] *= a0; O[ni][2] *= a1; O[ni][3] *= a1;
        }

        // ---- O += P V (3-term split), V^T via ldmatrix.trans ----
        #pragma unroll
        for (int ki = 0; ki < 4; ++ki) {
            #pragma unroll
            for (int nb = 0; nb < 8; ++nb) {
                uint32_t vh[4], vl[4];
                ldm_x4t(vh[0], vh[1], vh[2], vh[3],
                        va + ki*(16*ROWB) + nb*32);
                ldm_x4t(vl[0], vl[1], vl[2], vl[3],
                        va + AKL + ki*(16*ROWB) + nb*32);
                mma_bf16(O[2*nb],   phi[ki], vh[0], vh[1]);
                mma_bf16(O[2*nb],   phi[ki], vl[0], vl[1]);
                mma_bf16(O[2*nb],   plo[ki], vh[0], vh[1]);
                mma_bf16(O[2*nb+1], phi[ki], vh[2], vh[3]);
                mma_bf16(O[2*nb+1], phi[ki], vl[2], vl[3]);
                mma_bf16(O[2*nb+1], plo[ki], vh[2], vh[3]);
            }
        }
    }

    // ---- epilogue: normalize, split to bf16 hi/lo, store ----
    float il0 = 1.0f / l0, il1 = 1.0f / l1;
    size_t r0 = qrow + 16*w + (lane >> 2);
    int colb = h * DH + 2 * (lane & 3);
    #pragma unroll
    for (int ni = 0; ni < 16; ++ni) {
        int col = colb + 8 * ni;
        store_split(g_Ah, g_Al, r0 * EMB + col,
                    O[ni][0] * il0, O[ni][1] * il0);
        store_split(g_Ah, g_Al, (r0 + 8) * EMB + col,
                    O[ni][2] * il1, O[ni][3] * il1);
    }
}

// ==================== launch ===============================================
extern "C" void kernel_launch(void* const* d_in, const int* in_sizes, int n_in,
                              void* d_out, int out_size) {
    const float* x  = (const float*)d_in[0];
    const float* Wq = (const float*)d_in[1];
    const float* Wk = (const float*)d_in[2];
    const float* Wv = (const float*)d_in[3];
    const float* Wo = (const float*)d_in[4];
    const float* bo = (const float*)d_in[5];
    float* out = (float*)d_out;
    (void)in_sizes; (void)n_in; (void)out_size;

    void *pXh, *pXl, *pAh, *pAl, *pWth, *pWtl, *pWoth, *pWotl, *pCh, *pCl;
    cudaGetSymbolAddress(&pXh, g_Xh);     cudaGetSymbolAddress(&pXl, g_Xl);
    cudaGetSymbolAddress(&pAh, g_Ah);     cudaGetSymbolAddress(&pAl, g_Al);
    cudaGetSymbolAddress(&pWth, g_Wth);   cudaGetSymbolAddress(&pWtl, g_Wtl);
    cudaGetSymbolAddress(&pWoth, g_Woth); cudaGetSymbolAddress(&pWotl, g_Wotl);
    cudaGetSymbolAddress(&pCh, g_Ch);     cudaGetSymbolAddress(&pCl, g_Cl);

    cudaFuncSetAttribute(gemm_mma, cudaFuncAttributeMaxDynamicSharedMemorySize, GSMEM);
    cudaFuncSetAttribute(attn_mma, cudaFuncAttributeMaxDynamicSharedMemorySize, ATT_SMEM);

    // 1) split x; transpose+split weights
    split_vec<<<4096, 256>>>(x, (__nv_bfloat16*)pXh, (__nv_bfloat16*)pXl,
                             MROWS * EMB / 4);
    tsplit<<<dim3(64, 64), dim3(32, 8)>>>(Wq, (__nv_bfloat16*)pWth, (__nv_bfloat16*)pWtl, 2048, 0);
    tsplit<<<dim3(4,  64), dim3(32, 8)>>>(Wk, (__nv_bfloat16*)pWth, (__nv_bfloat16*)pWtl, 128, 2048);
    tsplit<<<dim3(4,  64), dim3(32, 8)>>>(Wv, (__nv_bfloat16*)pWth, (__nv_bfloat16*)pWtl, 128, 2176);
    tsplit<<<dim3(64, 64), dim3(32, 8)>>>(Wo, (__nv_bfloat16*)pWoth, (__nv_bfloat16*)pWotl, 2048, 0);

    // 2) fused QKV projection -> split bf16 g_Ch/g_Cl
    gemm_mma<<<dim3(NQKV / 128, MROWS / 256), 256, GSMEM>>>(
        (const __nv_bfloat16*)pXh, (const __nv_bfloat16*)pXl,
        (const __nv_bfloat16*)pWth, (const __nv_bfloat16*)pWtl,
        (__nv_bfloat16*)pCh, (__nv_bfloat16*)pCl, nullptr, nullptr, NQKV);

    // 3) tensor-core causal MQA flash attention -> split bf16 g_Ah/g_Al
    attn_mma<<<dim3(TLEN / 128, NH, BSZ), 256, ATT_SMEM>>>();

    // 4) O-projection with fused bias -> fp32 out
    gemm_mma<<<dim3(EMB / 128, MROWS / 256), 256, GSMEM>>>(
        (const __nv_bfloat16*)pAh, (const __nv_bfloat16*)pAl,
        (const __nv_bfloat16*)pWoth, (const __nv_bfloat16*)pWotl,
        nullptr, nullptr, out, bo, EMB);
}

// round 13
// speedup vs baseline: 5.7554x; 1.0002x over previous
#include <cuda_runtime.h>
#include <cuda_bf16.h>
#include <stdint.h>
#include <math.h>

#define EMB   2048
#define NH    16
#define DH    128
#define BSZ   4
#define TLEN  2048
#define MROWS (BSZ*TLEN)   // 8192
#define NQKV  2304         // 2048 (Q heads) + 128 (K) + 128 (V)
#define GK    2048         // GEMM K depth

// ---------------- scratch (static device globals; no allocations) ----------
__device__ __nv_bfloat16 g_Xh[MROWS*GK],  g_Xl[MROWS*GK];    // split x
__device__ __nv_bfloat16 g_Ch[MROWS*NQKV], g_Cl[MROWS*NQKV]; // split QKV out
__device__ __nv_bfloat16 g_Ah[MROWS*EMB], g_Al[MROWS*EMB];   // split attn out
__device__ __nv_bfloat16 g_Wth[NQKV*GK],  g_Wtl[NQKV*GK];    // [Wq|Wk|Wv]^T [N,K]
__device__ __nv_bfloat16 g_Woth[EMB*GK],  g_Wotl[EMB*GK];    // Wo^T [N,K]

// ==================== helpers ==============================================
__device__ __forceinline__ uint32_t smem_u32(const void* p) {
    uint32_t a;
    asm("{ .reg .u64 t; cvta.to.shared.u64 t, %1; cvt.u32.u64 %0, t; }"
        : "=r"(a) : "l"(p));
    return a;
}
__device__ __forceinline__ void cp_async16(uint32_t dst, const void* src) {
    asm volatile("cp.async.cg.shared.global [%0], [%1], 16;\n"
                 :: "r"(dst), "l"(src));
}
#define CP_COMMIT()  asm volatile("cp.async.commit_group;\n" ::: "memory")
#define CP_WAIT(n)   asm volatile("cp.async.wait_group %0;\n" :: "n"(n) : "memory")

__device__ __forceinline__ void ldm_x4(uint32_t& r0, uint32_t& r1,
                                       uint32_t& r2, uint32_t& r3, uint32_t a) {
    asm volatile("ldmatrix.sync.aligned.m8n8.x4.shared.b16 {%0,%1,%2,%3}, [%4];"
                 : "=r"(r0), "=r"(r1), "=r"(r2), "=r"(r3) : "r"(a));
}
__device__ __forceinline__ void ldm_x4t(uint32_t& r0, uint32_t& r1,
                                        uint32_t& r2, uint32_t& r3, uint32_t a) {
    asm volatile("ldmatrix.sync.aligned.m8n8.x4.trans.shared.b16 {%0,%1,%2,%3}, [%4];"
                 : "=r"(r0), "=r"(r1), "=r"(r2), "=r"(r3) : "r"(a));
}
__device__ __forceinline__ void mma_bf16(float* c, const uint32_t* a,
                                         uint32_t b0, uint32_t b1) {
    asm volatile(
        "mma.sync.aligned.m16n8k16.row.col.f32.bf16.bf16.f32 "
        "{%0,%1,%2,%3}, {%4,%5,%6,%7}, {%8,%9}, {%0,%1,%2,%3};"
        : "+f"(c[0]), "+f"(c[1]), "+f"(c[2]), "+f"(c[3])
        : "r"(a[0]), "r"(a[1]), "r"(a[2]), "r"(a[3]), "r"(b0), "r"(b1));
}
__device__ __forceinline__ uint32_t b2u(__nv_bfloat162 v) {
    union { __nv_bfloat162 b; uint32_t u; } cv; cv.b = v; return cv.u;
}
__device__ __forceinline__ void store_split(__nv_bfloat16* Ch, __nv_bfloat16* Cl,
                                            size_t off, float v0, float v1) {
    __nv_bfloat16 h0 = __float2bfloat16(v0), h1 = __float2bfloat16(v1);
    *(__nv_bfloat162*)(Ch + off) = __halves2bfloat162(h0, h1);
    *(__nv_bfloat162*)(Cl + off) = __halves2bfloat162(
        __float2bfloat16(v0 - __bfloat162float(h0)),
        __float2bfloat16(v1 - __bfloat162float(h1)));
}

// ==================== conversion kernels ===================================
__device__ __forceinline__ void split1(float v, __nv_bfloat16& h, __nv_bfloat16& l) {
    h = __float2bfloat16(v);
    l = __float2bfloat16(v - __bfloat162float(h));
}

__global__ void split_vec(const float* __restrict__ src,
                          __nv_bfloat16* __restrict__ h,
                          __nv_bfloat16* __restrict__ l, int n4) {
    int i = blockIdx.x * blockDim.x + threadIdx.x;
    int stride = gridDim.x * blockDim.x;
    __nv_bfloat162* H = (__nv_bfloat162*)h;
    __nv_bfloat162* L = (__nv_bfloat162*)l;
    for (; i < n4; i += stride) {
        float4 v = ((const float4*)src)[i];
        __nv_bfloat16 h0, l0, h1, l1, h2, l2, h3, l3;
        split1(v.x, h0, l0); split1(v.y, h1, l1);
        split1(v.z, h2, l2); split1(v.w, h3, l3);
        H[2*i]     = __halves2bfloat162(h0, h1);
        H[2*i + 1] = __halves2bfloat162(h2, h3);
        L[2*i]     = __halves2bfloat162(l0, l1);
        L[2*i + 1] = __halves2bfloat162(l2, l3);
    }
}

__global__ void tsplit(const float* __restrict__ src,
                       __nv_bfloat16* __restrict__ dh,
                       __nv_bfloat16* __restrict__ dl, int N, int rowOff) {
    __shared__ float t[32][33];
    int n0 = blockIdx.x * 32, k0 = blockIdx.y * 32;
    int tx = threadIdx.x, ty = threadIdx.y;     // 32 x 8
    #pragma unroll
    for (int r = 0; r < 4; r++)
        t[ty + r*8][tx] = src[(size_t)(k0 + ty + r*8) * N + n0 + tx];
    __syncthreads();
    #pragma unroll
    for (int r = 0; r < 4; r++) {
        int n = n0 + ty + r*8, k = k0 + tx;
        float v = t[tx][ty + r*8];
        __nv_bfloat16 h, l; split1(v, h, l);
        size_t o = (size_t)(n + rowOff) * GK + k;
        dh[o] = h; dl[o] = l;
    }
}

// ==================== mma.sync split-bf16 GEMM =============================
// C[M,N] = A[M,K] * B[N,K]^T via 3-term bf16 split.
// CTA 128x128, 8 warps (2 in M x 4 in N), warp tile 64x32.
// K-chunk 32, 2-stage cp.async, 2 CTAs/SM (latency hiding).
#define KC      32
#define LDSE    40                       // bf16 elems per smem row (32+8 pad)
#define ROW2    (LDSE*2)                 // 80 B
// stage rows: [0,128) A-hi | [128,256) A-lo | [256,384) B-hi | [384,512) B-lo
#define AL_OFF  (128*ROW2)
#define BH_OFF  (256*ROW2)
#define BL_OFF  (384*ROW2)
#define STAGE_B (512*ROW2)               // 40960 B
#define GSMEM   (2*STAGE_B)              // 81920 B
#define NCHUNK  (GK/KC)                  // 64

__global__ __launch_bounds__(256, 2)
void gemm_mma(const __nv_bfloat16* __restrict__ Ah, const __nv_bfloat16* __restrict__ Al,
              const __nv_bfloat16* __restrict__ Bh, const __nv_bfloat16* __restrict__ Bl,
              __nv_bfloat16* __restrict__ Ch, __nv_bfloat16* __restrict__ Cl,
              float* __restrict__ Cf, const float* __restrict__ bias, int ldc) {
    extern __shared__ char smem[];
    const uint32_t sb = smem_u32(smem);

    const int tid  = threadIdx.x;
    const int wid  = tid >> 5;
    const int lane = tid & 31;
    const int wm   = wid >> 2;           // 0..1 : 64-row group
    const int wn   = wid & 3;            // 0..3 : 32-col group
    const int row0 = blockIdx.y * 128;
    const int n0   = blockIdx.x * 128;

    const __nv_bfloat16* pAh = Ah + (size_t)row0 * GK;
    const __nv_bfloat16* pAl = Al + (size_t)row0 * GK;
    const __nv_bfloat16* pBh = Bh + (size_t)n0 * GK;
    const __nv_bfloat16* pBl = Bl + (size_t)n0 * GK;

    float acc[4][4][4];
    #pragma unroll
    for (int i = 0; i < 4; i++)
        #pragma unroll
        for (int j = 0; j < 4; j++) {
            acc[i][j][0] = 0.f; acc[i][j][1] = 0.f;
            acc[i][j][2] = 0.f; acc[i][j][3] = 0.f;
        }

    const int a_row = wm * 64 + (lane & 15);
    const int a_col = (lane >> 4) * 8;
    const int b_g   = lane >> 3;
    const int b_row = wn * 32 + ((b_g >> 1) * 8) + (lane & 7);
    const int b_col = (b_g & 1) * 8;

    // cp.async: 2048 16B chunks per stage, 8 per thread
    auto load_stage = [&](int s, int c) {
        const uint32_t st = sb + s * STAGE_B;
        const int k0 = c * KC;
        #pragma unroll
        for (int it = 0; it < 8; ++it) {
            int f = tid + it * 256;          // 0..2047
            int r = f >> 2;                  // smem row 0..511
            int c16 = f & 3;
            uint32_t so = (uint32_t)(r * ROW2 + c16 * 16);
            const __nv_bfloat16* src;
            if (r < 128)      src = pAh + (size_t)r * GK + k0 + c16 * 8;
            else if (r < 256) src = pAl + (size_t)(r - 128) * GK + k0 + c16 * 8;
            else if (r < 384) src = pBh + (size_t)(r - 256) * GK + k0 + c16 * 8;
            else              src = pBl + (size_t)(r - 384) * GK + k0 + c16 * 8;
            cp_async16(st + so, src);
        }
        CP_COMMIT();
    };

    load_stage(0, 0);

    for (int c = 0; c < NCHUNK; ++c) {
        CP_WAIT(0);
        __syncthreads();
        if (c + 1 < NCHUNK) load_stage((c + 1) & 1, c + 1);

        const uint32_t st = sb + (c & 1) * STAGE_B;

        #pragma unroll
        for (int ks = 0; ks < 2; ++ks) {
            uint32_t bh[8], bl[8];
            #pragma unroll
            for (int nb = 0; nb < 2; ++nb) {
                uint32_t off = (uint32_t)((b_row + nb*16) * ROW2
                                          + (b_col + ks*16) * 2);
                ldm_x4(bh[nb*4+0], bh[nb*4+1], bh[nb*4+2], bh[nb*4+3],
                       st + BH_OFF + off);
                ldm_x4(bl[nb*4+0], bl[nb*4+1], bl[nb*4+2], bl[nb*4+3],
                       st + BL_OFF + off);
            }
            #pragma unroll
            for (int mi = 0; mi < 4; ++mi) {
                uint32_t ah[4], al[4];
                uint32_t off = (uint32_t)((a_row + mi*16) * ROW2
                                          + (a_col + ks*16) * 2);
                ldm_x4(ah[0], ah[1], ah[2], ah[3], st + off);
                ldm_x4(al[0], al[1], al[2], al[3], st + AL_OFF + off);
                #pragma unroll
                for (int ni = 0; ni < 4; ++ni) {
                    uint32_t b0h = bh[ni*2], b1h = bh[ni*2+1];
                    uint32_t b0l = bl[ni*2], b1l = bl[ni*2+1];
                    mma_bf16(acc[mi][ni], ah, b0h, b1h);
                    mma_bf16(acc[mi][ni], ah, b0l, b1l);
                    mma_bf16(acc[mi][ni], al, b0h, b1h);
                }
            }
        }
    }

    const int er = lane >> 2;
    const int ec = (lane & 3) * 2;
    #pragma unroll
    for (int mi = 0; mi < 4; ++mi) {
        #pragma unroll
        for (int ni = 0; ni < 4; ++ni) {
            int gr = row0 + wm*64 + mi*16 + er;
            int gc = n0 + wn*32 + ni*8 + ec;
            if (Cf) {
                float bx = 0.f, by = 0.f;
                if (bias) { bx = bias[gc]; by = bias[gc + 1]; }
                float2 v0 = make_float2(acc[mi][ni][0] + bx, acc[mi][ni][1] + by);
                float2 v1 = make_float2(acc[mi][ni][2] + bx, acc[mi][ni][3] + by);
                *(float2*)&Cf[(size_t)gr * ldc + gc]       = v0;
                *(float2*)&Cf[(size_t)(gr + 8) * ldc + gc] = v1;
            } else {
                store_split(Ch, Cl, (size_t)gr * ldc + gc,
                            acc[mi][ni][0], acc[mi][ni][1]);
                store_split(Ch, Cl, (size_t)(gr + 8) * ldc + gc,
                            acc[mi][ni][2], acc[mi][ni][3]);
            }
        }
    }
}

// ==================== tensor-core causal MQA flash attention ===============
// Per CTA: (b, h, 256-row Q tile). 8 warps x 32 Q rows (2 m16 blocks).
// KV tiles of 32 keys, double-buffered. K/V fragment loads amortized over
// 32 rows/warp; warps skip fully-masked causal tiles.
#define LDA     136
#define ROWB    (LDA*2)                  // 272 B
#define QL_OFF  (256*ROWB)               // Q-lo
#define KV0     (512*ROWB)               // KV stages base
#define KVSTAGE (128*ROWB)               // Kh|Kl|Vh|Vl, 32 rows each
#define AKL     (32*ROWB)
#define AVH     (64*ROWB)
#define ATT_SMEM (KV0 + 2*KVSTAGE)       // 208896 B

__global__ __launch_bounds__(256, 1)
void attn_mma() {
    extern __shared__ char smc[];
    const uint32_t sb = smem_u32(smc);
    const int tid = threadIdx.x, w = tid >> 5, lane = tid & 31;
    const int qt = blockIdx.x, h = blockIdx.y, b = blockIdx.z;
    const int q0 = qt * 256;
    const size_t qrow = (size_t)(b * TLEN + q0);

    auto load_kv = [&](int jt, int s) {
        const size_t krow = (size_t)(b * TLEN + jt * 32);
        const uint32_t base = sb + KV0 + s * KVSTAGE;
        #pragma unroll
        for (int it = 0; it < 8; ++it) {
            int f = tid + it * 256;          // 0..2047
            int arr = f >> 9;                // 0 Kh,1 Kl,2 Vh,3 Vl
            int r   = (f >> 4) & 31;
            int c   = f & 15;
            const __nv_bfloat16* src = ((arr & 1) ? g_Cl : g_Ch)
                + (krow + r) * NQKV + ((arr < 2) ? 2048 : 2176) + c * 8;
            cp_async16(base + arr * AKL + r * ROWB + c * 16, src);
        }
        CP_COMMIT();
    };

    // ---- prefetch Q tile (256 rows hi+lo) + first KV tile ----
    #pragma unroll
    for (int it = 0; it < 32; ++it) {
        int f = tid + it * 256;              // 0..8191
        int arr = f >> 12;                   // 0=hi 1=lo
        int r   = (f >> 4) & 255;
        int c   = f & 15;
        const __nv_bfloat16* src = (arr ? g_Cl : g_Ch)
            + (qrow + r) * NQKV + h * DH + c * 8;
        cp_async16(sb + arr * QL_OFF + r * ROWB + c * 16, src);
    }
    load_kv(0, 0);   // commits Q + KV0 together

    const int bg = lane >> 3;
    const uint32_t qa = sb + (32*w + (lane & 15)) * ROWB + ((lane >> 4) * 8) * 2;
    const uint32_t koff = (((bg >> 1) * 8) + (lane & 7)) * ROWB + ((bg & 1) * 8) * 2;
    const uint32_t voff = (((bg & 1) * 8) + (lane & 7)) * ROWB + ((bg >> 1) * 8) * 2;

    float O[2][16][4];
    #pragma unroll
    for (int mi = 0; mi < 2; mi++)
        #pragma unroll
        for (int i = 0; i < 16; i++) {
            O[mi][i][0]=0.f; O[mi][i][1]=0.f; O[mi][i][2]=0.f; O[mi][i][3]=0.f;
        }
    float m[2][2], l[2][2];
    m[0][0]=m[0][1]=m[1][0]=m[1][1] = -1e30f;
    l[0][0]=l[0][1]=l[1][0]=l[1][1] = 0.f;
    const float scale = 0.08838834764831845f;   // 1/sqrt(128)

    const int ntile = 8 * qt + 8;
    for (int jt = 0; jt < ntile; ++jt) {
        CP_WAIT(0);
        __syncthreads();
        if (jt + 1 < ntile) load_kv(jt + 1, (jt + 1) & 1);

        // fully-masked for this warp? (keys all strictly future of warp's rows)
        if (jt * 32 > q0 + 32*w + 31) continue;

        const uint32_t st = sb + KV0 + (jt & 1) * KVSTAGE;
        const uint32_t ka = st + koff;
        const uint32_t va = st + AVH + voff;

        // ---- S = Q K^T (3-term split): 32 rows x 32 keys per warp ----
        float S[2][4][4];
        #pragma unroll
        for (int mi = 0; mi < 2; mi++)
            #pragma unroll
            for (int i = 0; i < 4; i++) {
                S[mi][i][0]=0.f; S[mi][i][1]=0.f; S[mi][i][2]=0.f; S[mi][i][3]=0.f;
            }

        #pragma unroll
        for (int ks = 0; ks < 8; ++ks) {
            uint32_t ah[2][4], al[2][4];
            #pragma unroll
            for (int mi = 0; mi < 2; ++mi) {
                ldm_x4(ah[mi][0], ah[mi][1], ah[mi][2], ah[mi][3],
                       qa + mi*(16*ROWB) + ks*32);
                ldm_x4(al[mi][0], al[mi][1], al[mi][2], al[mi][3],
                       qa + QL_OFF + mi*(16*ROWB) + ks*32);
            }
            #pragma unroll
            for (int nn = 0; nn < 2; ++nn) {
                uint32_t kh[4], kl[4];
                ldm_x4(kh[0], kh[1], kh[2], kh[3],
                       ka + nn*(16*ROWB) + ks*32);
                ldm_x4(kl[0], kl[1], kl[2], kl[3],
                       ka + AKL + nn*(16*ROWB) + ks*32);
                #pragma unroll
                for (int mi = 0; mi < 2; ++mi) {
                    mma_bf16(S[mi][2*nn],   ah[mi], kh[0], kh[1]);
                    mma_bf16(S[mi][2*nn],   ah[mi], kl[0], kl[1]);
                    mma_bf16(S[mi][2*nn],   al[mi], kh[0], kh[1]);
                    mma_bf16(S[mi][2*nn+1], ah[mi], kh[2], kh[3]);
                    mma_bf16(S[mi][2*nn+1], ah[mi], kl[2], kl[3]);
                    mma_bf16(S[mi][2*nn+1], al[mi], kh[2], kh[3]);
                }
            }
        }

        // ---- scale + causal mask + online softmax (per 16-row block) ----
        const bool edge = (jt * 32 + 31 > q0 + 32*w);
        const int cb = jt*32 + 2*(lane & 3);
        uint32_t phi[2][2][4], plo[2][2][4];
        #pragma unroll
        for (int mi = 0; mi < 2; ++mi) {
            const int gr0 = q0 + 32*w + 16*mi + (lane >> 2);
            #pragma unroll
            for (int nt = 0; nt < 4; ++nt) {
                S[mi][nt][0] *= scale; S[mi][nt][1] *= scale;
                S[mi][nt][2] *= scale; S[mi][nt][3] *= scale;
            }
            if (edge) {
                #pragma unroll
                for (int nt = 0; nt < 4; ++nt) {
                    int gk = cb + 8*nt;
                    if (gk     > gr0)     S[mi][nt][0] = -1e30f;
                    if (gk + 1 > gr0)     S[mi][nt][1] = -1e30f;
                    if (gk     > gr0 + 8) S[mi][nt][2] = -1e30f;
                    if (gk + 1 > gr0 + 8) S[mi][nt][3] = -1e30f;
                }
            }

            float rm0 = -1e30f, rm1 = -1e30f;
            #pragma unroll
            for (int nt = 0; nt < 4; ++nt) {
                rm0 = fmaxf(rm0, fmaxf(S[mi][nt][0], S[mi][nt][1]));
                rm1 = fmaxf(rm1, fmaxf(S[mi][nt][2], S[mi][nt][3]));
            }
            rm0 = fmaxf(rm0, __shfl_xor_sync(0xffffffffu, rm0, 1));
            rm0 = fmaxf(rm0, __shfl_xor_sync(0xffffffffu, rm0, 2));
            rm1 = fmaxf(rm1, __shfl_xor_sync(0xffffffffu, rm1, 1));
            rm1 = fmaxf(rm1, __shfl_xor_sync(0xffffffffu, rm1, 2));
            float mn0 = fmaxf(m[mi][0], rm0), mn1 = fmaxf(m[mi][1], rm1);
            float a0 = __expf(m[mi][0] - mn0), a1 = __expf(m[mi][1] - mn1);
            m[mi][0] = mn0; m[mi][1] = mn1;

            float rs0 = 0.f, rs1 = 0.f;
            #pragma unroll
            for (int nt = 0; nt < 4; ++nt) {
                float p0 = __expf(S[mi][nt][0] - mn0), p1 = __expf(S[mi][nt][1] - mn0);
                float p2 = __expf(S[mi][nt][2] - mn1), p3 = __expf(S[mi][nt][3] - mn1);
                rs0 += p0 + p1;  rs1 += p2 + p3;
                __nv_bfloat16 h0 = __float2bfloat16(p0), h1 = __float2bfloat16(p1);
                __nv_bfloat16 h2 = __float2bfloat16(p2), h3 = __float2bfloat16(p3);
                int ki = nt >> 1, sl = (nt & 1) * 2;
                phi[mi][ki][sl+0] = b2u(__halves2bfloat162(h0, h1));
                phi[mi][ki][sl+1] = b2u(__halves2bfloat162(h2, h3));
                plo[mi][ki][sl+0] = b2u(__halves2bfloat162(
                    __float2bfloat16(p0 - __bfloat162float(h0)),
                    __float2bfloat16(p1 - __bfloat162float(h1))));
                plo[mi][ki][sl+1] = b2u(__halves2bfloat162(
                    __float2bfloat16(p2 - __bfloat162float(h2)),
                    __float2bfloat16(p3 - __bfloat162float(h3))));
            }
            rs0 += __shfl_xor_sync(0xffffffffu, rs0, 1);
            rs0 += __shfl_xor_sync(0xffffffffu, rs0, 2);
            rs1 += __shfl_xor_sync(0xffffffffu, rs1, 1);
            rs1 += __shfl_xor_sync(0xffffffffu, rs1, 2);
            l[mi][0] = l[mi][0] * a0 + rs0;
            l[mi][1] = l[mi][1] * a1 + rs1;

            #pragma unroll
            for (int ni = 0; ni < 16; ++ni) {
                O[mi][ni][0] *= a0; O[mi][ni][1] *= a0;
                O[mi][ni][2] *= a1; O[mi][ni][3] *= a1;
            }
        }

        // ---- O += P V (3-term split); V frags shared across both mi ----
        #pragma unroll
        for (int ki = 0; ki < 2; ++ki) {
            #pragma unroll
            for (int nb = 0; nb < 8; ++nb) {
                uint32_t vh[4], vl[4];
                ldm_x4t(vh[0], vh[1], vh[2], vh[3],
                        va + ki*(16*ROWB) + nb*32);
                ldm_x4t(vl[0], vl[1], vl[2], vl[3],
                        va + AKL + ki*(16*ROWB) + nb*32);
                #pragma unroll
                for (int mi = 0; mi < 2; ++mi) {
                    mma_bf16(O[mi][2*nb],   phi[mi][ki], vh[0], vh[1]);
                    mma_bf16(O[mi][2*nb],   phi[mi][ki], vl[0], vl[1]);
                    mma_bf16(O[mi][2*nb],   plo[mi][ki], vh[0], vh[1]);
                    mma_bf16(O[mi][2*nb+1], phi[mi][ki], vh[2], vh[3]);
                    mma_bf16(O[mi][2*nb+1], phi[mi][ki], vl[2], vl[3]);
                    mma_bf16(O[mi][2*nb+1], plo[mi][ki], vh[2], vh[3]);
                }
            }
        }
    }

    // ---- epilogue: normalize, split to bf16 hi/lo, store ----
    #pragma unroll
    for (int mi = 0; mi < 2; ++mi) {
        float il0 = 1.0f / l[mi][0], il1 = 1.0f / l[mi][1];
        size_t r0 = qrow + 32*w + 16*mi + (lane >> 2);
        int colb = h * DH + 2 * (lane & 3);
        #pragma unroll
        for (int ni = 0; ni < 16; ++ni) {
            int col = colb + 8 * ni;
            store_split(g_Ah, g_Al, r0 * EMB + col,
                        O[mi][ni][0] * il0, O[mi][ni][1] * il0);
            store_split(g_Ah, g_Al, (r0 + 8) * EMB + col,
                        O[mi][ni][2] * il1, O[mi][ni][3] * il1);
        }
    }
}

// ==================== launch ===============================================
extern "C" void kernel_launch(void* const* d_in, const int* in_sizes, int n_in,
                              void* d_out, int out_size) {
    const float* x  = (const float*)d_in[0];
    const float* Wq = (const float*)d_in[1];
    const float* Wk = (const float*)d_in[2];
    const float* Wv = (const float*)d_in[3];
    const float* Wo = (const float*)d_in[4];
    const float* bo = (const float*)d_in[5];
    float* out = (float*)d_out;
    (void)in_sizes; (void)n_in; (void)out_size;

    void *pXh, *pXl, *pAh, *pAl, *pWth, *pWtl, *pWoth, *pWotl, *pCh, *pCl;
    cudaGetSymbolAddress(&pXh, g_Xh);     cudaGetSymbolAddress(&pXl, g_Xl);
    cudaGetSymbolAddress(&pAh, g_Ah);     cudaGetSymbolAddress(&pAl, g_Al);
    cudaGetSymbolAddress(&pWth, g_Wth);   cudaGetSymbolAddress(&pWtl, g_Wtl);
    cudaGetSymbolAddress(&pWoth, g_Woth); cudaGetSymbolAddress(&pWotl, g_Wotl);
    cudaGetSymbolAddress(&pCh, g_Ch);     cudaGetSymbolAddress(&pCl, g_Cl);

    cudaFuncSetAttribute(gemm_mma, cudaFuncAttributeMaxDynamicSharedMemorySize, GSMEM);
    cudaFuncSetAttribute(attn_mma, cudaFuncAttributeMaxDynamicSharedMemorySize, ATT_SMEM);

    // 1) split x; transpose+split weights
    split_vec<<<4096, 256>>>(x, (__nv_bfloat16*)pXh, (__nv_bfloat16*)pXl,
                             MROWS * EMB / 4);
    tsplit<<<dim3(64, 64), dim3(32, 8)>>>(Wq, (__nv_bfloat16*)pWth, (__nv_bfloat16*)pWtl, 2048, 0);
    tsplit<<<dim3(4,  64), dim3(32, 8)>>>(Wk, (__nv_bfloat16*)pWth, (__nv_bfloat16*)pWtl, 128, 2048);
    tsplit<<<dim3(4,  64), dim3(32, 8)>>>(Wv, (__nv_bfloat16*)pWth, (__nv_bfloat16*)pWtl, 128, 2176);
    tsplit<<<dim3(64, 64), dim3(32, 8)>>>(Wo, (__nv_bfloat16*)pWoth, (__nv_bfloat16*)pWotl, 2048, 0);

    // 2) fused QKV projection -> split bf16 g_Ch/g_Cl
    gemm_mma<<<dim3(NQKV / 128, MROWS / 128), 256, GSMEM>>>(
        (const __nv_bfloat16*)pXh, (const __nv_bfloat16*)pXl,
        (const __nv_bfloat16*)pWth, (const __nv_bfloat16*)pWtl,
        (__nv_bfloat16*)pCh, (__nv_bfloat16*)pCl, nullptr, nullptr, NQKV);

    // 3) tensor-core causal MQA flash attention -> split bf16 g_Ah/g_Al
    attn_mma<<<dim3(TLEN / 256, NH, BSZ), 256, ATT_SMEM>>>();

    // 4) O-projection with fused bias -> fp32 out
    gemm_mma<<<dim3(EMB / 128, MROWS / 128), 256, GSMEM>>>(
        (const __nv_bfloat16*)pAh, (const __nv_bfloat16*)pAl,
        (const __nv_bfloat16*)pWoth, (const __nv_bfloat16*)pWotl,
        nullptr, nullptr, out, bo, EMB);
}

// round 14
// speedup vs baseline: 6.5068x; 1.1306x over previous
#include <cuda_runtime.h>
#include <cuda_fp16.h>
#include <stdint.h>
#include <math.h>

#define EMB   2048
#define NH    16
#define DH    128
#define BSZ   4
#define TLEN  2048
#define MROWS (BSZ*TLEN)   // 8192
#define NQKV  2304         // 2048 (Q heads) + 128 (K) + 128 (V)
#define GK    2048         // GEMM K depth

// ---------------- scratch (static device globals; no allocations) ----------
__device__ __half g_Xh[MROWS*GK],  g_Xl[MROWS*GK];    // split x
__device__ __half g_Ch[MROWS*NQKV], g_Cl[MROWS*NQKV]; // split QKV out
__device__ __half g_Ah[MROWS*EMB], g_Al[MROWS*EMB];   // split attn out
__device__ __half g_Wth[NQKV*GK],  g_Wtl[NQKV*GK];    // [Wq|Wk|Wv]^T [N,K]
__device__ __half g_Woth[EMB*GK],  g_Wotl[EMB*GK];    // Wo^T [N,K] (lo unused)

// ==================== helpers ==============================================
__device__ __forceinline__ uint32_t smem_u32(const void* p) {
    uint32_t a;
    asm("{ .reg .u64 t; cvta.to.shared.u64 t, %1; cvt.u32.u64 %0, t; }"
        : "=r"(a) : "l"(p));
    return a;
}
__device__ __forceinline__ void cp_async16(uint32_t dst, const void* src) {
    asm volatile("cp.async.cg.shared.global [%0], [%1], 16;\n"
                 :: "r"(dst), "l"(src));
}
#define CP_COMMIT()  asm volatile("cp.async.commit_group;\n" ::: "memory")
#define CP_WAIT(n)   asm volatile("cp.async.wait_group %0;\n" :: "n"(n) : "memory")

__device__ __forceinline__ void ldm_x4(uint32_t& r0, uint32_t& r1,
                                       uint32_t& r2, uint32_t& r3, uint32_t a) {
    asm volatile("ldmatrix.sync.aligned.m8n8.x4.shared.b16 {%0,%1,%2,%3}, [%4];"
                 : "=r"(r0), "=r"(r1), "=r"(r2), "=r"(r3) : "r"(a));
}
__device__ __forceinline__ void ldm_x4t(uint32_t& r0, uint32_t& r1,
                                        uint32_t& r2, uint32_t& r3, uint32_t a) {
    asm volatile("ldmatrix.sync.aligned.m8n8.x4.trans.shared.b16 {%0,%1,%2,%3}, [%4];"
                 : "=r"(r0), "=r"(r1), "=r"(r2), "=r"(r3) : "r"(a));
}
__device__ __forceinline__ void mma_f16(float* c, const uint32_t* a,
                                        uint32_t b0, uint32_t b1) {
    asm volatile(
        "mma.sync.aligned.m16n8k16.row.col.f32.f16.f16.f32 "
        "{%0,%1,%2,%3}, {%4,%5,%6,%7}, {%8,%9}, {%0,%1,%2,%3};"
        : "+f"(c[0]), "+f"(c[1]), "+f"(c[2]), "+f"(c[3])
        : "r"(a[0]), "r"(a[1]), "r"(a[2]), "r"(a[3]), "r"(b0), "r"(b1));
}
__device__ __forceinline__ uint32_t h2u(__half2 v) {
    union { __half2 h; uint32_t u; } cv; cv.h = v; return cv.u;
}
__device__ __forceinline__ void store_split(__half* Ch, __half* Cl,
                                            size_t off, float v0, float v1) {
    __half h0 = __float2half(v0), h1 = __float2half(v1);
    *(__half2*)(Ch + off) = __halves2half2(h0, h1);
    *(__half2*)(Cl + off) = __halves2half2(
        __float2half(v0 - __half2float(h0)),
        __float2half(v1 - __half2float(h1)));
}
__device__ __forceinline__ void split1(float v, __half& h, __half& l) {
    h = __float2half(v);
    l = __float2half(v - __half2float(h));
}

// ==================== conversion kernels ===================================
__global__ void split_vec(const float* __restrict__ src,
                          __half* __restrict__ h,
                          __half* __restrict__ l, int n4) {
    int i = blockIdx.x * blockDim.x + threadIdx.x;
    int stride = gridDim.x * blockDim.x;
    __half2* H = (__half2*)h;
    __half2* L = (__half2*)l;
    for (; i < n4; i += stride) {
        float4 v = ((const float4*)src)[i];
        __half h0, l0, h1, l1, h2, l2, h3, l3;
        split1(v.x, h0, l0); split1(v.y, h1, l1);
        split1(v.z, h2, l2); split1(v.w, h3, l3);
        H[2*i]     = __halves2half2(h0, h1);
        H[2*i + 1] = __halves2half2(h2, h3);
        L[2*i]     = __halves2half2(l0, l1);
        L[2*i + 1] = __halves2half2(l2, l3);
    }
}

// fused transpose+split for Wq|Wk|Wv -> g_Wth/g_Wtl rows [0,2304)
__global__ void tsplit_qkv(const float* __restrict__ Wq,
                           const float* __restrict__ Wk,
                           const float* __restrict__ Wv,
                           __half* __restrict__ dh, __half* __restrict__ dl) {
    __shared__ float t[32][33];
    const float* src; int N, n0, rowOff;
    int nb = blockIdx.x;
    if (nb < 64)      { src = Wq; N = 2048; n0 = nb * 32;        rowOff = 0; }
    else if (nb < 68) { src = Wk; N = 128;  n0 = (nb - 64) * 32; rowOff = 2048; }
    else              { src = Wv; N = 128;  n0 = (nb - 68) * 32; rowOff = 2176; }
    int k0 = blockIdx.y * 32;
    int tx = threadIdx.x, ty = threadIdx.y;     // 32 x 8
    #pragma unroll
    for (int r = 0; r < 4; r++)
        t[ty + r*8][tx] = src[(size_t)(k0 + ty + r*8) * N + n0 + tx];
    __syncthreads();
    #pragma unroll
    for (int r = 0; r < 4; r++) {
        int n = n0 + ty + r*8, k = k0 + tx;
        __half h, l; split1(t[tx][ty + r*8], h, l);
        size_t o = (size_t)(n + rowOff) * GK + k;
        dh[o] = h; dl[o] = l;
    }
}

// transpose+split (hi only used downstream) for Wo
__global__ void tsplit(const float* __restrict__ src,
                       __half* __restrict__ dh, __half* __restrict__ dl, int N) {
    __shared__ float t[32][33];
    int n0 = blockIdx.x * 32, k0 = blockIdx.y * 32;
    int tx = threadIdx.x, ty = threadIdx.y;
    #pragma unroll
    for (int r = 0; r < 4; r++)
        t[ty + r*8][tx] = src[(size_t)(k0 + ty + r*8) * N + n0 + tx];
    __syncthreads();
    #pragma unroll
    for (int r = 0; r < 4; r++) {
        int n = n0 + ty + r*8, k = k0 + tx;
        __half h, l; split1(t[tx][ty + r*8], h, l);
        size_t o = (size_t)n * GK + k;
        dh[o] = h; dl[o] = l;
    }
}

// ==================== mma.sync split-fp16 GEMM =============================
// TERMS=3: C = Ah*Bh + Ah*Bl + Al*Bh  (residual ~2^-22)
// TERMS=2: C = Ah*Bh + Al*Bh = A*Bh   (error = A*Bl ~ 2.8e-4 RMS)
// CTA 128x128, 8 warps (2 in M x 4 in N), warp tile 64x32, K-chunk 32,
// 2-stage cp.async, 2 CTAs/SM.
#define KC      32
#define LDSE    40
#define ROW2    (LDSE*2)                 // 80 B
#define AL_OFF  (128*ROW2)
#define BH_OFF  (256*ROW2)
#define BL_OFF  (384*ROW2)
#define STAGE_B (512*ROW2)               // 40960 B
#define GSMEM   (2*STAGE_B)              // 81920 B
#define NCHUNK  (GK/KC)                  // 64

template<int TERMS>
__global__ __launch_bounds__(256, 2)
void gemm_mma(const __half* __restrict__ Ah, const __half* __restrict__ Al,
              const __half* __restrict__ Bh, const __half* __restrict__ Bl,
              __half* __restrict__ Ch, __half* __restrict__ Cl,
              float* __restrict__ Cf, const float* __restrict__ bias, int ldc) {
    extern __shared__ char smem[];
    const uint32_t sb = smem_u32(smem);

    const int tid  = threadIdx.x;
    const int wid  = tid >> 5;
    const int lane = tid & 31;
    const int wm   = wid >> 2;
    const int wn   = wid & 3;
    const int row0 = blockIdx.y * 128;
    const int n0   = blockIdx.x * 128;

    const __half* pAh = Ah + (size_t)row0 * GK;
    const __half* pAl = Al + (size_t)row0 * GK;
    const __half* pBh = Bh + (size_t)n0 * GK;
    const __half* pBl = (TERMS == 3) ? Bl + (size_t)n0 * GK : nullptr;

    float acc[4][4][4];
    #pragma unroll
    for (int i = 0; i < 4; i++)
        #pragma unroll
        for (int j = 0; j < 4; j++) {
            acc[i][j][0] = 0.f; acc[i][j][1] = 0.f;
            acc[i][j][2] = 0.f; acc[i][j][3] = 0.f;
        }

    const int a_row = wm * 64 + (lane & 15);
    const int a_col = (lane >> 4) * 8;
    const int b_g   = lane >> 3;
    const int b_row = wn * 32 + ((b_g >> 1) * 8) + (lane & 7);
    const int b_col = (b_g & 1) * 8;

    auto load_stage = [&](int s, int c) {
        const uint32_t st = sb + s * STAGE_B;
        const int k0 = c * KC;
        #pragma unroll
        for (int it = 0; it < 8; ++it) {
            int f = tid + it * 256;
            int r = f >> 2;
            int c16 = f & 3;
            if (TERMS == 2 && r >= 384) continue;
            uint32_t so = (uint32_t)(r * ROW2 + c16 * 16);
            const __half* src;
            if (r < 128)      src = pAh + (size_t)r * GK + k0 + c16 * 8;
            else if (r < 256) src = pAl + (size_t)(r - 128) * GK + k0 + c16 * 8;
            else if (r < 384) src = pBh + (size_t)(r - 256) * GK + k0 + c16 * 8;
            else              src = pBl + (size_t)(r - 384) * GK + k0 + c16 * 8;
            cp_async16(st + so, src);
        }
        CP_COMMIT();
    };

    load_stage(0, 0);

    for (int c = 0; c < NCHUNK; ++c) {
        CP_WAIT(0);
        __syncthreads();
        if (c + 1 < NCHUNK) load_stage((c + 1) & 1, c + 1);

        const uint32_t st = sb + (c & 1) * STAGE_B;

        #pragma unroll
        for (int ks = 0; ks < 2; ++ks) {
            uint32_t bh[8], bl[8];
            #pragma unroll
            for (int nb = 0; nb < 2; ++nb) {
                uint32_t off = (uint32_t)((b_row + nb*16) * ROW2
                                          + (b_col + ks*16) * 2);
                ldm_x4(bh[nb*4+0], bh[nb*4+1], bh[nb*4+2], bh[nb*4+3],
                       st + BH_OFF + off);
                if (TERMS == 3)
                    ldm_x4(bl[nb*4+0], bl[nb*4+1], bl[nb*4+2], bl[nb*4+3],
                           st + BL_OFF + off);
            }
            #pragma unroll
            for (int mi = 0; mi < 4; ++mi) {
                uint32_t ah[4], al[4];
                uint32_t off = (uint32_t)((a_row + mi*16) * ROW2
                                          + (a_col + ks*16) * 2);
                ldm_x4(ah[0], ah[1], ah[2], ah[3], st + off);
                ldm_x4(al[0], al[1], al[2], al[3], st + AL_OFF + off);
                #pragma unroll
                for (int ni = 0; ni < 4; ++ni) {
                    mma_f16(acc[mi][ni], ah, bh[ni*2], bh[ni*2+1]);
                    if (TERMS == 3)
                        mma_f16(acc[mi][ni], ah, bl[ni*2], bl[ni*2+1]);
                    mma_f16(acc[mi][ni], al, bh[ni*2], bh[ni*2+1]);
                }
            }
        }
    }

    const int er = lane >> 2;
    const int ec = (lane & 3) * 2;
    #pragma unroll
    for (int mi = 0; mi < 4; ++mi) {
        #pragma unroll
        for (int ni = 0; ni < 4; ++ni) {
            int gr = row0 + wm*64 + mi*16 + er;
            int gc = n0 + wn*32 + ni*8 + ec;
            if (Cf) {
                float bx = 0.f, by = 0.f;
                if (bias) { bx = bias[gc]; by = bias[gc + 1]; }
                float2 v0 = make_float2(acc[mi][ni][0] + bx, acc[mi][ni][1] + by);
                float2 v1 = make_float2(acc[mi][ni][2] + bx, acc[mi][ni][3] + by);
                *(float2*)&Cf[(size_t)gr * ldc + gc]       = v0;
                *(float2*)&Cf[(size_t)(gr + 8) * ldc + gc] = v1;
            } else {
                store_split(Ch, Cl, (size_t)gr * ldc + gc,
                            acc[mi][ni][0], acc[mi][ni][1]);
                store_split(Ch, Cl, (size_t)(gr + 8) * ldc + gc,
                            acc[mi][ni][2], acc[mi][ni][3]);
            }
        }
    }
}

// ==================== tensor-core causal MQA flash attention ===============
// Per CTA: (b, h, 256-row Q tile). 8 warps x 32 Q rows.
// S = QK^T: 3-term fp16 split. PV: 2-term (P split exact, V single-rounded).
// KV tiles of 32 keys (Kh|Kl|Vh), double-buffered.
#define LDA     136
#define ROWB    (LDA*2)                  // 272 B
#define QL_OFF  (256*ROWB)
#define KV0     (512*ROWB)
#define AKL     (32*ROWB)                // Kl offset within stage
#define AVH     (64*ROWB)                // Vh offset within stage
#define KVSTAGE (96*ROWB)
#define ATT_SMEM (KV0 + 2*KVSTAGE)       // 191488 B

__global__ __launch_bounds__(256, 1)
void attn_mma() {
    extern __shared__ char smc[];
    const uint32_t sb = smem_u32(smc);
    const int tid = threadIdx.x, w = tid >> 5, lane = tid & 31;
    const int qt = blockIdx.x, h = blockIdx.y, b = blockIdx.z;
    const int q0 = qt * 256;
    const size_t qrow = (size_t)(b * TLEN + q0);

    auto load_kv = [&](int jt, int s) {
        const size_t krow = (size_t)(b * TLEN + jt * 32);
        const uint32_t base = sb + KV0 + s * KVSTAGE;
        #pragma unroll
        for (int it = 0; it < 6; ++it) {
            int f = tid + it * 256;          // 0..1535
            int arr = f >> 9;                // 0 Kh, 1 Kl, 2 Vh
            int r   = (f >> 4) & 31;
            int c   = f & 15;
            const __half* src;
            if (arr == 0)      src = g_Ch + (krow + r) * NQKV + 2048 + c * 8;
            else if (arr == 1) src = g_Cl + (krow + r) * NQKV + 2048 + c * 8;
            else               src = g_Ch + (krow + r) * NQKV + 2176 + c * 8;
            cp_async16(base + arr * AKL + r * ROWB + c * 16, src);
        }
        CP_COMMIT();
    };

    // ---- prefetch Q tile (256 rows hi+lo) + first KV tile ----
    #pragma unroll
    for (int it = 0; it < 32; ++it) {
        int f = tid + it * 256;              // 0..8191
        int arr = f >> 12;                   // 0=hi 1=lo
        int r   = (f >> 4) & 255;
        int c   = f & 15;
        const __half* src = (arr ? g_Cl : g_Ch)
            + (qrow + r) * NQKV + h * DH + c * 8;
        cp_async16(sb + arr * QL_OFF + r * ROWB + c * 16, src);
    }
    load_kv(0, 0);

    const int bg = lane >> 3;
    const uint32_t qa = sb + (32*w + (lane & 15)) * ROWB + ((lane >> 4) * 8) * 2;
    const uint32_t koff = (((bg >> 1) * 8) + (lane & 7)) * ROWB + ((bg & 1) * 8) * 2;
    const uint32_t voff = (((bg & 1) * 8) + (lane & 7)) * ROWB + ((bg >> 1) * 8) * 2;

    float O[2][16][4];
    #pragma unroll
    for (int mi = 0; mi < 2; mi++)
        #pragma unroll
        for (int i = 0; i < 16; i++) {
            O[mi][i][0]=0.f; O[mi][i][1]=0.f; O[mi][i][2]=0.f; O[mi][i][3]=0.f;
        }
    float m[2][2], l[2][2];
    m[0][0]=m[0][1]=m[1][0]=m[1][1] = -1e30f;
    l[0][0]=l[0][1]=l[1][0]=l[1][1] = 0.f;
    const float scale = 0.08838834764831845f;   // 1/sqrt(128)

    const int ntile = 8 * qt + 8;
    for (int jt = 0; jt < ntile; ++jt) {
        CP_WAIT(0);
        __syncthreads();
        if (jt + 1 < ntile) load_kv(jt + 1, (jt + 1) & 1);

        if (jt * 32 > q0 + 32*w + 31) continue;   // fully masked for this warp

        const uint32_t st = sb + KV0 + (jt & 1) * KVSTAGE;
        const uint32_t ka = st + koff;
        const uint32_t va = st + AVH + voff;

        // ---- S = Q K^T (3-term split) ----
        float S[2][4][4];
        #pragma unroll
        for (int mi = 0; mi < 2; mi++)
            #pragma unroll
            for (int i = 0; i < 4; i++) {
                S[mi][i][0]=0.f; S[mi][i][1]=0.f; S[mi][i][2]=0.f; S[mi][i][3]=0.f;
            }

        #pragma unroll
        for (int ks = 0; ks < 8; ++ks) {
            uint32_t ah[2][4], al[2][4];
            #pragma unroll
            for (int mi = 0; mi < 2; ++mi) {
                ldm_x4(ah[mi][0], ah[mi][1], ah[mi][2], ah[mi][3],
                       qa + mi*(16*ROWB) + ks*32);
                ldm_x4(al[mi][0], al[mi][1], al[mi][2], al[mi][3],
                       qa + QL_OFF + mi*(16*ROWB) + ks*32);
            }
            #pragma unroll
            for (int nn = 0; nn < 2; ++nn) {
                uint32_t kh[4], kl[4];
                ldm_x4(kh[0], kh[1], kh[2], kh[3],
                       ka + nn*(16*ROWB) + ks*32);
                ldm_x4(kl[0], kl[1], kl[2], kl[3],
                       ka + AKL + nn*(16*ROWB) + ks*32);
                #pragma unroll
                for (int mi = 0; mi < 2; ++mi) {
                    mma_f16(S[mi][2*nn],   ah[mi], kh[0], kh[1]);
                    mma_f16(S[mi][2*nn],   ah[mi], kl[0], kl[1]);
                    mma_f16(S[mi][2*nn],   al[mi], kh[0], kh[1]);
                    mma_f16(S[mi][2*nn+1], ah[mi], kh[2], kh[3]);
                    mma_f16(S[mi][2*nn+1], ah[mi], kl[2], kl[3]);
                    mma_f16(S[mi][2*nn+1], al[mi], kh[2], kh[3]);
                }
            }
        }

        // ---- scale + causal mask + online softmax ----
        const bool edge = (jt * 32 + 31 > q0 + 32*w);
        const int cb = jt*32 + 2*(lane & 3);
        uint32_t phi[2][2][4], plo[2][2][4];
        #pragma unroll
        for (int mi = 0; mi < 2; ++mi) {
            const int gr0 = q0 + 32*w + 16*mi + (lane >> 2);
            #pragma unroll
            for (int nt = 0; nt < 4; ++nt) {
                S[mi][nt][0] *= scale; S[mi][nt][1] *= scale;
                S[mi][nt][2] *= scale; S[mi][nt][3] *= scale;
            }
            if (edge) {
                #pragma unroll
                for (int nt = 0; nt < 4; ++nt) {
                    int gk = cb + 8*nt;
                    if (gk     > gr0)     S[mi][nt][0] = -1e30f;
                    if (gk + 1 > gr0)     S[mi][nt][1] = -1e30f;
                    if (gk     > gr0 + 8) S[mi][nt][2] = -1e30f;
                    if (gk + 1 > gr0 + 8) S[mi][nt][3] = -1e30f;
                }
            }

            float rm0 = -1e30f, rm1 = -1e30f;
            #pragma unroll
            for (int nt = 0; nt < 4; ++nt) {
                rm0 = fmaxf(rm0, fmaxf(S[mi][nt][0], S[mi][nt][1]));
                rm1 = fmaxf(rm1, fmaxf(S[mi][nt][2], S[mi][nt][3]));
            }
            rm0 = fmaxf(rm0, __shfl_xor_sync(0xffffffffu, rm0, 1));
            rm0 = fmaxf(rm0, __shfl_xor_sync(0xffffffffu, rm0, 2));
            rm1 = fmaxf(rm1, __shfl_xor_sync(0xffffffffu, rm1, 1));
            rm1 = fmaxf(rm1, __shfl_xor_sync(0xffffffffu, rm1, 2));
            float mn0 = fmaxf(m[mi][0], rm0), mn1 = fmaxf(m[mi][1], rm1);
            float a0 = __expf(m[mi][0] - mn0), a1 = __expf(m[mi][1] - mn1);
            m[mi][0] = mn0; m[mi][1] = mn1;

            float rs0 = 0.f, rs1 = 0.f;
            #pragma unroll
            for (int nt = 0; nt < 4; ++nt) {
                float p0 = __expf(S[mi][nt][0] - mn0), p1 = __expf(S[mi][nt][1] - mn0);
                float p2 = __expf(S[mi][nt][2] - mn1), p3 = __expf(S[mi][nt][3] - mn1);
                rs0 += p0 + p1;  rs1 += p2 + p3;
                __half h0 = __float2half(p0), h1 = __float2half(p1);
                __half h2 = __float2half(p2), h3 = __float2half(p3);
                int ki = nt >> 1, sl = (nt & 1) * 2;
                phi[mi][ki][sl+0] = h2u(__halves2half2(h0, h1));
                phi[mi][ki][sl+1] = h2u(__halves2half2(h2, h3));
                plo[mi][ki][sl+0] = h2u(__halves2half2(
                    __float2half(p0 - __half2float(h0)),
                    __float2half(p1 - __half2float(h1))));
                plo[mi][ki][sl+1] = h2u(__halves2half2(
                    __float2half(p2 - __half2float(h2)),
                    __float2half(p3 - __half2float(h3))));
            }
            rs0 += __shfl_xor_sync(0xffffffffu, rs0, 1);
            rs0 += __shfl_xor_sync(0xffffffffu, rs0, 2);
            rs1 += __shfl_xor_sync(0xffffffffu, rs1, 1);
            rs1 += __shfl_xor_sync(0xffffffffu, rs1, 2);
            l[mi][0] = l[mi][0] * a0 + rs0;
            l[mi][1] = l[mi][1] * a1 + rs1;

            #pragma unroll
            for (int ni = 0; ni < 16; ++ni) {
                O[mi][ni][0] *= a0; O[mi][ni][1] *= a0;
                O[mi][ni][2] *= a1; O[mi][ni][3] *= a1;
            }
        }

        // ---- O += P Vh (2-term: (Ph+Pl)*Vh) ----
        #pragma unroll
        for (int ki = 0; ki < 2; ++ki) {
            #pragma unroll
            for (int nb = 0; nb < 8; ++nb) {
                uint32_t vh[4];
                ldm_x4t(vh[0], vh[1], vh[2], vh[3],
                        va + ki*(16*ROWB) + nb*32);
                #pragma unroll
                for (int mi = 0; mi < 2; ++mi) {
                    mma_f16(O[mi][2*nb],   phi[mi][ki], vh[0], vh[1]);
                    mma_f16(O[mi][2*nb],   plo[mi][ki], vh[0], vh[1]);
                    mma_f16(O[mi][2*nb+1], phi[mi][ki], vh[2], vh[3]);
                    mma_f16(O[mi][2*nb+1], plo[mi][ki], vh[2], vh[3]);
                }
            }
        }
    }

    // ---- epilogue: normalize, split to fp16 hi/lo, store ----
    #pragma unroll
    for (int mi = 0; mi < 2; ++mi) {
        float il0 = 1.0f / l[mi][0], il1 = 1.0f / l[mi][1];
        size_t r0 = qrow + 32*w + 16*mi + (lane >> 2);
        int colb = h * DH + 2 * (lane & 3);
        #pragma unroll
        for (int ni = 0; ni < 16; ++ni) {
            int col = colb + 8 * ni;
            store_split(g_Ah, g_Al, r0 * EMB + col,
                        O[mi][ni][0] * il0, O[mi][ni][1] * il0);
            store_split(g_Ah, g_Al, (r0 + 8) * EMB + col,
                        O[mi][ni][2] * il1, O[mi][ni][3] * il1);
        }
    }
}

// ==================== launch ===============================================
extern "C" void kernel_launch(void* const* d_in, const int* in_sizes, int n_in,
                              void* d_out, int out_size) {
    const float* x  = (const float*)d_in[0];
    const float* Wq = (const float*)d_in[1];
    const float* Wk = (const float*)d_in[2];
    const float* Wv = (const float*)d_in[3];
    const float* Wo = (const float*)d_in[4];
    const float* bo = (const float*)d_in[5];
    float* out = (float*)d_out;
    (void)in_sizes; (void)n_in; (void)out_size;

    void *pXh, *pXl, *pAh, *pAl, *pWth, *pWtl, *pWoth, *pWotl, *pCh, *pCl;
    cudaGetSymbolAddress(&pXh, g_Xh);     cudaGetSymbolAddress(&pXl, g_Xl);
    cudaGetSymbolAddress(&pAh, g_Ah);     cudaGetSymbolAddress(&pAl, g_Al);
    cudaGetSymbolAddress(&pWth, g_Wth);   cudaGetSymbolAddress(&pWtl, g_Wtl);
    cudaGetSymbolAddress(&pWoth, g_Woth); cudaGetSymbolAddress(&pWotl, g_Wotl);
    cudaGetSymbolAddress(&pCh, g_Ch);     cudaGetSymbolAddress(&pCl, g_Cl);

    cudaFuncSetAttribute(gemm_mma<3>, cudaFuncAttributeMaxDynamicSharedMemorySize, GSMEM);
    cudaFuncSetAttribute(gemm_mma<2>, cudaFuncAttributeMaxDynamicSharedMemorySize, GSMEM);
    cudaFuncSetAttribute(attn_mma, cudaFuncAttributeMaxDynamicSharedMemorySize, ATT_SMEM);

    // 1) split x; transpose+split weights (QKV fused into one launch)
    split_vec<<<4096, 256>>>(x, (__half*)pXh, (__half*)pXl, MROWS * EMB / 4);
    tsplit_qkv<<<dim3(72, 64), dim3(32, 8)>>>(Wq, Wk, Wv,
                                              (__half*)pWth, (__half*)pWtl);
    tsplit<<<dim3(64, 64), dim3(32, 8)>>>(Wo, (__half*)pWoth, (__half*)pWotl, 2048);

    // 2) fused QKV projection (3-term) -> split fp16 g_Ch/g_Cl
    gemm_mma<3><<<dim3(NQKV / 128, MROWS / 128), 256, GSMEM>>>(
        (const __half*)pXh, (const __half*)pXl,
        (const __half*)pWth, (const __half*)pWtl,
        (__half*)pCh, (__half*)pCl, nullptr, nullptr, NQKV);

    // 3) tensor-core causal MQA flash attention -> split fp16 g_Ah/g_Al
    attn_mma<<<dim3(TLEN / 256, NH, BSZ), 256, ATT_SMEM>>>();

    // 4) O-projection (2-term, Wo single-rounded) with fused bias -> fp32 out
    gemm_mma<2><<<dim3(EMB / 128, MROWS / 128), 256, GSMEM>>>(
        (const __half*)pAh, (const __half*)pAl,
        (const __half*)pWoth, (const __half*)pWotl,
        nullptr, nullptr, out, bo, EMB);
}

// round 15
// speedup vs baseline: 7.5318x; 1.1575x over previous
#include <cuda_runtime.h>
#include <cuda_fp16.h>
#include <stdint.h>
#include <math.h>

#define EMB   2048
#define NH    16
#define DH    128
#define BSZ   4
#define TLEN  2048
#define MROWS (BSZ*TLEN)   // 8192
#define NQKV  2304         // 2048 (Q heads) + 128 (K) + 128 (V)
#define GK    2048         // GEMM K depth

// ---------------- scratch (static device globals; no allocations) ----------
__device__ __half g_Xh[MROWS*GK],  g_Xl[MROWS*GK];    // split x
__device__ __half g_Ch[MROWS*NQKV], g_Cl[MROWS*NQKV]; // split QKV out
__device__ __half g_Ah[MROWS*EMB], g_Al[MROWS*EMB];   // split attn out
__device__ __half g_Wth[NQKV*GK];                     // [Wq|Wk|Wv]^T [N,K] hi
__device__ __half g_Woth[EMB*GK];                     // Wo^T [N,K] hi

// ==================== helpers ==============================================
__device__ __forceinline__ uint32_t smem_u32(const void* p) {
    uint32_t a;
    asm("{ .reg .u64 t; cvta.to.shared.u64 t, %1; cvt.u32.u64 %0, t; }"
        : "=r"(a) : "l"(p));
    return a;
}
__device__ __forceinline__ void cp_async16(uint32_t dst, const void* src) {
    asm volatile("cp.async.cg.shared.global [%0], [%1], 16;\n"
                 :: "r"(dst), "l"(src));
}
#define CP_COMMIT()  asm volatile("cp.async.commit_group;\n" ::: "memory")
#define CP_WAIT(n)   asm volatile("cp.async.wait_group %0;\n" :: "n"(n) : "memory")

__device__ __forceinline__ void ldm_x4(uint32_t& r0, uint32_t& r1,
                                       uint32_t& r2, uint32_t& r3, uint32_t a) {
    asm volatile("ldmatrix.sync.aligned.m8n8.x4.shared.b16 {%0,%1,%2,%3}, [%4];"
                 : "=r"(r0), "=r"(r1), "=r"(r2), "=r"(r3) : "r"(a));
}
__device__ __forceinline__ void ldm_x4t(uint32_t& r0, uint32_t& r1,
                                        uint32_t& r2, uint32_t& r3, uint32_t a) {
    asm volatile("ldmatrix.sync.aligned.m8n8.x4.trans.shared.b16 {%0,%1,%2,%3}, [%4];"
                 : "=r"(r0), "=r"(r1), "=r"(r2), "=r"(r3) : "r"(a));
}
__device__ __forceinline__ void mma_f16(float* c, const uint32_t* a,
                                        uint32_t b0, uint32_t b1) {
    asm volatile(
        "mma.sync.aligned.m16n8k16.row.col.f32.f16.f16.f32 "
        "{%0,%1,%2,%3}, {%4,%5,%6,%7}, {%8,%9}, {%0,%1,%2,%3};"
        : "+f"(c[0]), "+f"(c[1]), "+f"(c[2]), "+f"(c[3])
        : "r"(a[0]), "r"(a[1]), "r"(a[2]), "r"(a[3]), "r"(b0), "r"(b1));
}
__device__ __forceinline__ uint32_t h2u(__half2 v) {
    union { __half2 h; uint32_t u; } cv; cv.h = v; return cv.u;
}
__device__ __forceinline__ void store_split(__half* Ch, __half* Cl,
                                            size_t off, float v0, float v1) {
    __half h0 = __float2half(v0), h1 = __float2half(v1);
    *(__half2*)(Ch + off) = __halves2half2(h0, h1);
    *(__half2*)(Cl + off) = __halves2half2(
        __float2half(v0 - __half2float(h0)),
        __float2half(v1 - __half2float(h1)));
}
__device__ __forceinline__ void split1(float v, __half& h, __half& l) {
    h = __float2half(v);
    l = __float2half(v - __half2float(h));
}

// ==================== conversion kernels ===================================
__global__ void split_vec(const float* __restrict__ src,
                          __half* __restrict__ h,
                          __half* __restrict__ l, int n4) {
    int i = blockIdx.x * blockDim.x + threadIdx.x;
    int stride = gridDim.x * blockDim.x;
    __half2* H = (__half2*)h;
    __half2* L = (__half2*)l;
    for (; i < n4; i += stride) {
        float4 v = ((const float4*)src)[i];
        __half h0, l0, h1, l1, h2, l2, h3, l3;
        split1(v.x, h0, l0); split1(v.y, h1, l1);
        split1(v.z, h2, l2); split1(v.w, h3, l3);
        H[2*i]     = __halves2half2(h0, h1);
        H[2*i + 1] = __halves2half2(h2, h3);
        L[2*i]     = __halves2half2(l0, l1);
        L[2*i + 1] = __halves2half2(l2, l3);
    }
}

// fused transpose (hi only) for Wq|Wk|Wv -> g_Wth rows [0,2304)
__global__ void tsplit_qkv(const float* __restrict__ Wq,
                           const float* __restrict__ Wk,
                           const float* __restrict__ Wv,
                           __half* __restrict__ dh) {
    __shared__ float t[32][33];
    const float* src; int N, n0, rowOff;
    int nb = blockIdx.x;
    if (nb < 64)      { src = Wq; N = 2048; n0 = nb * 32;        rowOff = 0; }
    else if (nb < 68) { src = Wk; N = 128;  n0 = (nb - 64) * 32; rowOff = 2048; }
    else              { src = Wv; N = 128;  n0 = (nb - 68) * 32; rowOff = 2176; }
    int k0 = blockIdx.y * 32;
    int tx = threadIdx.x, ty = threadIdx.y;     // 32 x 8
    #pragma unroll
    for (int r = 0; r < 4; r++)
        t[ty + r*8][tx] = src[(size_t)(k0 + ty + r*8) * N + n0 + tx];
    __syncthreads();
    #pragma unroll
    for (int r = 0; r < 4; r++) {
        int n = n0 + ty + r*8, k = k0 + tx;
        dh[(size_t)(n + rowOff) * GK + k] = __float2half(t[tx][ty + r*8]);
    }
}

// transpose (hi only) for Wo
__global__ void tsplit(const float* __restrict__ src,
                       __half* __restrict__ dh, int N) {
    __shared__ float t[32][33];
    int n0 = blockIdx.x * 32, k0 = blockIdx.y * 32;
    int tx = threadIdx.x, ty = threadIdx.y;
    #pragma unroll
    for (int r = 0; r < 4; r++)
        t[ty + r*8][tx] = src[(size_t)(k0 + ty + r*8) * N + n0 + tx];
    __syncthreads();
    #pragma unroll
    for (int r = 0; r < 4; r++) {
        int n = n0 + ty + r*8, k = k0 + tx;
        dh[(size_t)n * GK + k] = __float2half(t[tx][ty + r*8]);
    }
}

// ==================== mma.sync 2-term fp16 GEMM ============================
// C = (Ah+Al)*Bh  (exact in A; error = A*Bl ~ 2.8e-4 RMS relative).
// CTA 128x128, 8 warps (2 in M x 4 in N), warp tile 64x32, K-chunk 32,
// 2-stage cp.async, 2 CTAs/SM.
#define KC      32
#define LDSE    40
#define ROW2    (LDSE*2)                 // 80 B
// stage rows: [0,128) A-hi | [128,256) A-lo | [256,384) B-hi
#define AL_OFF  (128*ROW2)
#define BH_OFF  (256*ROW2)
#define STAGE_B (384*ROW2)               // 30720 B
#define GSMEM   (2*STAGE_B)              // 61440 B
#define NCHUNK  (GK/KC)                  // 64

__global__ __launch_bounds__(256, 2)
void gemm_mma(const __half* __restrict__ Ah, const __half* __restrict__ Al,
              const __half* __restrict__ Bh,
              __half* __restrict__ Ch, __half* __restrict__ Cl,
              float* __restrict__ Cf, const float* __restrict__ bias, int ldc) {
    extern __shared__ char smem[];
    const uint32_t sb = smem_u32(smem);

    const int tid  = threadIdx.x;
    const int wid  = tid >> 5;
    const int lane = tid & 31;
    const int wm   = wid >> 2;
    const int wn   = wid & 3;
    const int row0 = blockIdx.y * 128;
    const int n0   = blockIdx.x * 128;

    const __half* pAh = Ah + (size_t)row0 * GK;
    const __half* pAl = Al + (size_t)row0 * GK;
    const __half* pBh = Bh + (size_t)n0 * GK;

    float acc[4][4][4];
    #pragma unroll
    for (int i = 0; i < 4; i++)
        #pragma unroll
        for (int j = 0; j < 4; j++) {
            acc[i][j][0] = 0.f; acc[i][j][1] = 0.f;
            acc[i][j][2] = 0.f; acc[i][j][3] = 0.f;
        }

    const int a_row = wm * 64 + (lane & 15);
    const int a_col = (lane >> 4) * 8;
    const int b_g   = lane >> 3;
    const int b_row = wn * 32 + ((b_g >> 1) * 8) + (lane & 7);
    const int b_col = (b_g & 1) * 8;

    // cp.async: 1536 16B chunks per stage, 6 per thread
    auto load_stage = [&](int s, int c) {
        const uint32_t st = sb + s * STAGE_B;
        const int k0 = c * KC;
        #pragma unroll
        for (int it = 0; it < 6; ++it) {
            int f = tid + it * 256;          // 0..1535
            int r = f >> 2;                  // smem row 0..383
            int c16 = f & 3;
            uint32_t so = (uint32_t)(r * ROW2 + c16 * 16);
            const __half* src;
            if (r < 128)      src = pAh + (size_t)r * GK + k0 + c16 * 8;
            else if (r < 256) src = pAl + (size_t)(r - 128) * GK + k0 + c16 * 8;
            else              src = pBh + (size_t)(r - 256) * GK + k0 + c16 * 8;
            cp_async16(st + so, src);
        }
        CP_COMMIT();
    };

    load_stage(0, 0);

    for (int c = 0; c < NCHUNK; ++c) {
        CP_WAIT(0);
        __syncthreads();
        if (c + 1 < NCHUNK) load_stage((c + 1) & 1, c + 1);

        const uint32_t st = sb + (c & 1) * STAGE_B;

        #pragma unroll
        for (int ks = 0; ks < 2; ++ks) {
            uint32_t bh[8];
            #pragma unroll
            for (int nb = 0; nb < 2; ++nb) {
                uint32_t off = (uint32_t)((b_row + nb*16) * ROW2
                                          + (b_col + ks*16) * 2);
                ldm_x4(bh[nb*4+0], bh[nb*4+1], bh[nb*4+2], bh[nb*4+3],
                       st + BH_OFF + off);
            }
            #pragma unroll
            for (int mi = 0; mi < 4; ++mi) {
                uint32_t ah[4], al[4];
                uint32_t off = (uint32_t)((a_row + mi*16) * ROW2
                                          + (a_col + ks*16) * 2);
                ldm_x4(ah[0], ah[1], ah[2], ah[3], st + off);
                ldm_x4(al[0], al[1], al[2], al[3], st + AL_OFF + off);
                #pragma unroll
                for (int ni = 0; ni < 4; ++ni) {
                    mma_f16(acc[mi][ni], ah, bh[ni*2], bh[ni*2+1]);
                    mma_f16(acc[mi][ni], al, bh[ni*2], bh[ni*2+1]);
                }
            }
        }
    }

    const int er = lane >> 2;
    const int ec = (lane & 3) * 2;
    #pragma unroll
    for (int mi = 0; mi < 4; ++mi) {
        #pragma unroll
        for (int ni = 0; ni < 4; ++ni) {
            int gr = row0 + wm*64 + mi*16 + er;
            int gc = n0 + wn*32 + ni*8 + ec;
            if (Cf) {
                float bx = 0.f, by = 0.f;
                if (bias) { bx = bias[gc]; by = bias[gc + 1]; }
                float2 v0 = make_float2(acc[mi][ni][0] + bx, acc[mi][ni][1] + by);
                float2 v1 = make_float2(acc[mi][ni][2] + bx, acc[mi][ni][3] + by);
                *(float2*)&Cf[(size_t)gr * ldc + gc]       = v0;
                *(float2*)&Cf[(size_t)(gr + 8) * ldc + gc] = v1;
            } else {
                store_split(Ch, Cl, (size_t)gr * ldc + gc,
                            acc[mi][ni][0], acc[mi][ni][1]);
                store_split(Ch, Cl, (size_t)(gr + 8) * ldc + gc,
                            acc[mi][ni][2], acc[mi][ni][3]);
            }
        }
    }
}

// ==================== tensor-core causal MQA flash attention ===============
// Per CTA: (b, h, 256-row Q tile). 8 warps x 32 Q rows.
// S = (Qh+Ql)*Kh (2-term). PV = (Ph+Pl)*Vh (2-term).
// KV tiles of 32 keys (Kh|Vh), double-buffered.
#define LDA     136
#define ROWB    (LDA*2)                  // 272 B
#define QL_OFF  (256*ROWB)
#define KV0     (512*ROWB)
#define AVH     (32*ROWB)                // Vh offset within stage
#define KVSTAGE (64*ROWB)
#define ATT_SMEM (KV0 + 2*KVSTAGE)       // 174080 B

__global__ __launch_bounds__(256, 1)
void attn_mma() {
    extern __shared__ char smc[];
    const uint32_t sb = smem_u32(smc);
    const int tid = threadIdx.x, w = tid >> 5, lane = tid & 31;
    const int qt = blockIdx.x, h = blockIdx.y, b = blockIdx.z;
    const int q0 = qt * 256;
    const size_t qrow = (size_t)(b * TLEN + q0);

    auto load_kv = [&](int jt, int s) {
        const size_t krow = (size_t)(b * TLEN + jt * 32);
        const uint32_t base = sb + KV0 + s * KVSTAGE;
        #pragma unroll
        for (int it = 0; it < 4; ++it) {
            int f = tid + it * 256;          // 0..1023
            int arr = f >> 9;                // 0 Kh, 1 Vh
            int r   = (f >> 4) & 31;
            int c   = f & 15;
            const __half* src = g_Ch + (krow + r) * NQKV
                                + (arr ? 2176 : 2048) + c * 8;
            cp_async16(base + arr * AVH + r * ROWB + c * 16, src);
        }
        CP_COMMIT();
    };

    // ---- prefetch Q tile (256 rows hi+lo) + first KV tile ----
    #pragma unroll
    for (int it = 0; it < 32; ++it) {
        int f = tid + it * 256;              // 0..8191
        int arr = f >> 12;                   // 0=hi 1=lo
        int r   = (f >> 4) & 255;
        int c   = f & 15;
        const __half* src = (arr ? g_Cl : g_Ch)
            + (qrow + r) * NQKV + h * DH + c * 8;
        cp_async16(sb + arr * QL_OFF + r * ROWB + c * 16, src);
    }
    load_kv(0, 0);

    const int bg = lane >> 3;
    const uint32_t qa = sb + (32*w + (lane & 15)) * ROWB + ((lane >> 4) * 8) * 2;
    const uint32_t koff = (((bg >> 1) * 8) + (lane & 7)) * ROWB + ((bg & 1) * 8) * 2;
    const uint32_t voff = (((bg & 1) * 8) + (lane & 7)) * ROWB + ((bg >> 1) * 8) * 2;

    float O[2][16][4];
    #pragma unroll
    for (int mi = 0; mi < 2; mi++)
        #pragma unroll
        for (int i = 0; i < 16; i++) {
            O[mi][i][0]=0.f; O[mi][i][1]=0.f; O[mi][i][2]=0.f; O[mi][i][3]=0.f;
        }
    float m[2][2], l[2][2];
    m[0][0]=m[0][1]=m[1][0]=m[1][1] = -1e30f;
    l[0][0]=l[0][1]=l[1][0]=l[1][1] = 0.f;
    const float scale = 0.08838834764831845f;   // 1/sqrt(128)

    const int ntile = 8 * qt + 8;
    for (int jt = 0; jt < ntile; ++jt) {
        CP_WAIT(0);
        __syncthreads();
        if (jt + 1 < ntile) load_kv(jt + 1, (jt + 1) & 1);

        if (jt * 32 > q0 + 32*w + 31) continue;   // fully masked for this warp

        const uint32_t st = sb + KV0 + (jt & 1) * KVSTAGE;
        const uint32_t ka = st + koff;
        const uint32_t va = st + AVH + voff;

        // ---- S = Q K^T (2-term: (Qh+Ql)*Kh) ----
        float S[2][4][4];
        #pragma unroll
        for (int mi = 0; mi < 2; mi++)
            #pragma unroll
            for (int i = 0; i < 4; i++) {
                S[mi][i][0]=0.f; S[mi][i][1]=0.f; S[mi][i][2]=0.f; S[mi][i][3]=0.f;
            }

        #pragma unroll
        for (int ks = 0; ks < 8; ++ks) {
            uint32_t ah[2][4], al[2][4];
            #pragma unroll
            for (int mi = 0; mi < 2; ++mi) {
                ldm_x4(ah[mi][0], ah[mi][1], ah[mi][2], ah[mi][3],
                       qa + mi*(16*ROWB) + ks*32);
                ldm_x4(al[mi][0], al[mi][1], al[mi][2], al[mi][3],
                       qa + QL_OFF + mi*(16*ROWB) + ks*32);
            }
            #pragma unroll
            for (int nn = 0; nn < 2; ++nn) {
                uint32_t kh[4];
                ldm_x4(kh[0], kh[1], kh[2], kh[3],
                       ka + nn*(16*ROWB) + ks*32);
                #pragma unroll
                for (int mi = 0; mi < 2; ++mi) {
                    mma_f16(S[mi][2*nn],   ah[mi], kh[0], kh[1]);
                    mma_f16(S[mi][2*nn],   al[mi], kh[0], kh[1]);
                    mma_f16(S[mi][2*nn+1], ah[mi], kh[2], kh[3]);
                    mma_f16(S[mi][2*nn+1], al[mi], kh[2], kh[3]);
                }
            }
        }

        // ---- scale + causal mask + online softmax ----
        const bool edge = (jt * 32 + 31 > q0 + 32*w);
        const int cb = jt*32 + 2*(lane & 3);
        uint32_t phi[2][2][4], plo[2][2][4];
        #pragma unroll
        for (int mi = 0; mi < 2; ++mi) {
            const int gr0 = q0 + 32*w + 16*mi + (lane >> 2);
            #pragma unroll
            for (int nt = 0; nt < 4; ++nt) {
                S[mi][nt][0] *= scale; S[mi][nt][1] *= scale;
                S[mi][nt][2] *= scale; S[mi][nt][3] *= scale;
            }
            if (edge) {
                #pragma unroll
                for (int nt = 0; nt < 4; ++nt) {
                    int gk = cb + 8*nt;
                    if (gk     > gr0)     S[mi][nt][0] = -1e30f;
                    if (gk + 1 > gr0)     S[mi][nt][1] = -1e30f;
                    if (gk     > gr0 + 8) S[mi][nt][2] = -1e30f;
                    if (gk + 1 > gr0 + 8) S[mi][nt][3] = -1e30f;
                }
            }

            float rm0 = -1e30f, rm1 = -1e30f;
            #pragma unroll
            for (int nt = 0; nt < 4; ++nt) {
                rm0 = fmaxf(rm0, fmaxf(S[mi][nt][0], S[mi][nt][1]));
                rm1 = fmaxf(rm1, fmaxf(S[mi][nt][2], S[mi][nt][3]));
            }
            rm0 = fmaxf(rm0, __shfl_xor_sync(0xffffffffu, rm0, 1));
            rm0 = fmaxf(rm0, __shfl_xor_sync(0xffffffffu, rm0, 2));
            rm1 = fmaxf(rm1, __shfl_xor_sync(0xffffffffu, rm1, 1));
            rm1 = fmaxf(rm1, __shfl_xor_sync(0xffffffffu, rm1, 2));
            float mn0 = fmaxf(m[mi][0], rm0), mn1 = fmaxf(m[mi][1], rm1);
            float a0 = __expf(m[mi][0] - mn0), a1 = __expf(m[mi][1] - mn1);
            m[mi][0] = mn0; m[mi][1] = mn1;

            float rs0 = 0.f, rs1 = 0.f;
            #pragma unroll
            for (int nt = 0; nt < 4; ++nt) {
                float p0 = __expf(S[mi][nt][0] - mn0), p1 = __expf(S[mi][nt][1] - mn0);
                float p2 = __expf(S[mi][nt][2] - mn1), p3 = __expf(S[mi][nt][3] - mn1);
                rs0 += p0 + p1;  rs1 += p2 + p3;
                __half h0 = __float2half(p0), h1 = __float2half(p1);
                __half h2 = __float2half(p2), h3 = __float2half(p3);
                int ki = nt >> 1, sl = (nt & 1) * 2;
                phi[mi][ki][sl+0] = h2u(__halves2half2(h0, h1));
                phi[mi][ki][sl+1] = h2u(__halves2half2(h2, h3));
                plo[mi][ki][sl+0] = h2u(__halves2half2(
                    __float2half(p0 - __half2float(h0)),
                    __float2half(p1 - __half2float(h1))));
                plo[mi][ki][sl+1] = h2u(__halves2half2(
                    __float2half(p2 - __half2float(h2)),
                    __float2half(p3 - __half2float(h3))));
            }
            rs0 += __shfl_xor_sync(0xffffffffu, rs0, 1);
            rs0 += __shfl_xor_sync(0xffffffffu, rs0, 2);
            rs1 += __shfl_xor_sync(0xffffffffu, rs1, 1);
            rs1 += __shfl_xor_sync(0xffffffffu, rs1, 2);
            l[mi][0] = l[mi][0] * a0 + rs0;
            l[mi][1] = l[mi][1] * a1 + rs1;

            #pragma unroll
            for (int ni = 0; ni < 16; ++ni) {
                O[mi][ni][0] *= a0; O[mi][ni][1] *= a0;
                O[mi][ni][2] *= a1; O[mi][ni][3] *= a1;
            }
        }

        // ---- O += P Vh (2-term: (Ph+Pl)*Vh) ----
        #pragma unroll
        for (int ki = 0; ki < 2; ++ki) {
            #pragma unroll
            for (int nb = 0; nb < 8; ++nb) {
                uint32_t vh[4];
                ldm_x4t(vh[0], vh[1], vh[2], vh[3],
                        va + ki*(16*ROWB) + nb*32);
                #pragma unroll
                for (int mi = 0; mi < 2; ++mi) {
                    mma_f16(O[mi][2*nb],   phi[mi][ki], vh[0], vh[1]);
                    mma_f16(O[mi][2*nb],   plo[mi][ki], vh[0], vh[1]);
                    mma_f16(O[mi][2*nb+1], phi[mi][ki], vh[2], vh[3]);
                    mma_f16(O[mi][2*nb+1], plo[mi][ki], vh[2], vh[3]);
                }
            }
        }
    }

    // ---- epilogue: normalize, split to fp16 hi/lo, store ----
    #pragma unroll
    for (int mi = 0; mi < 2; ++mi) {
        float il0 = 1.0f / l[mi][0], il1 = 1.0f / l[mi][1];
        size_t r0 = qrow + 32*w + 16*mi + (lane >> 2);
        int colb = h * DH + 2 * (lane & 3);
        #pragma unroll
        for (int ni = 0; ni < 16; ++ni) {
            int col = colb + 8 * ni;
            store_split(g_Ah, g_Al, r0 * EMB + col,
                        O[mi][ni][0] * il0, O[mi][ni][1] * il0);
            store_split(g_Ah, g_Al, (r0 + 8) * EMB + col,
                        O[mi][ni][2] * il1, O[mi][ni][3] * il1);
        }
    }
}

// ==================== launch ===============================================
extern "C" void kernel_launch(void* const* d_in, const int* in_sizes, int n_in,
                              void* d_out, int out_size) {
    const float* x  = (const float*)d_in[0];
    const float* Wq = (const float*)d_in[1];
    const float* Wk = (const float*)d_in[2];
    const float* Wv = (const float*)d_in[3];
    const float* Wo = (const float*)d_in[4];
    const float* bo = (const float*)d_in[5];
    float* out = (float*)d_out;
    (void)in_sizes; (void)n_in; (void)out_size;

    void *pXh, *pXl, *pAh, *pAl, *pWth, *pWoth, *pCh, *pCl;
    cudaGetSymbolAddress(&pXh, g_Xh);     cudaGetSymbolAddress(&pXl, g_Xl);
    cudaGetSymbolAddress(&pAh, g_Ah);     cudaGetSymbolAddress(&pAl, g_Al);
    cudaGetSymbolAddress(&pWth, g_Wth);   cudaGetSymbolAddress(&pWoth, g_Woth);
    cudaGetSymbolAddress(&pCh, g_Ch);     cudaGetSymbolAddress(&pCl, g_Cl);

    cudaFuncSetAttribute(gemm_mma, cudaFuncAttributeMaxDynamicSharedMemorySize, GSMEM);
    cudaFuncSetAttribute(attn_mma, cudaFuncAttributeMaxDynamicSharedMemorySize, ATT_SMEM);

    // 1) split x; transpose weights (hi only; QKV fused into one launch)
    split_vec<<<4096, 256>>>(x, (__half*)pXh, (__half*)pXl, MROWS * EMB / 4);
    tsplit_qkv<<<dim3(72, 64), dim3(32, 8)>>>(Wq, Wk, Wv, (__half*)pWth);
    tsplit<<<dim3(64, 64), dim3(32, 8)>>>(Wo, (__half*)pWoth, 2048);

    // 2) fused QKV projection (2-term) -> split fp16 g_Ch/g_Cl
    gemm_mma<<<dim3(NQKV / 128, MROWS / 128), 256, GSMEM>>>(
        (const __half*)pXh, (const __half*)pXl, (const __half*)pWth,
        (__half*)pCh, (__half*)pCl, nullptr, nullptr, NQKV);

    // 3) tensor-core causal MQA flash attention -> split fp16 g_Ah/g_Al
    attn_mma<<<dim3(TLEN / 256, NH, BSZ), 256, ATT_SMEM>>>();

    // 4) O-projection (2-term) with fused bias -> fp32 out
    gemm_mma<<<dim3(EMB / 128, MROWS / 128), 256, GSMEM>>>(
        (const __half*)pAh, (const __half*)pAl, (const __half*)pWoth,
        nullptr, nullptr, out, bo, EMB);
}

// round 16
// speedup vs baseline: 8.3833x; 1.1131x over previous
#include <cuda_runtime.h>
#include <cuda_fp16.h>
#include <stdint.h>
#include <math.h>

#define EMB   2048
#define NH    16
#define DH    128
#define BSZ   4
#define TLEN  2048
#define MROWS (BSZ*TLEN)   // 8192
#define NQKV  2304         // 2048 (Q heads) + 128 (K) + 128 (V)
#define GK    2048         // GEMM K depth

// ---------------- scratch (static device globals; no allocations) ----------
__device__ __half g_Xh[MROWS*GK],  g_Xl[MROWS*GK];    // split x
__device__ __half g_Ch[MROWS*NQKV], g_Cl[MROWS*NQKV]; // split QKV out
__device__ __half g_Ah[MROWS*EMB], g_Al[MROWS*EMB];   // split attn out
__device__ __half g_Wth[NQKV*GK];                     // [Wq|Wk|Wv]^T [N,K] hi
__device__ __half g_Woth[EMB*GK];                     // Wo^T [N,K] hi

// ==================== helpers ==============================================
__device__ __forceinline__ uint32_t smem_u32(const void* p) {
    uint32_t a;
    asm("{ .reg .u64 t; cvta.to.shared.u64 t, %1; cvt.u32.u64 %0, t; }"
        : "=r"(a) : "l"(p));
    return a;
}
__device__ __forceinline__ void cp_async16(uint32_t dst, const void* src) {
    asm volatile("cp.async.cg.shared.global [%0], [%1], 16;\n"
                 :: "r"(dst), "l"(src));
}
#define CP_COMMIT()  asm volatile("cp.async.commit_group;\n" ::: "memory")
#define CP_WAIT(n)   asm volatile("cp.async.wait_group %0;\n" :: "n"(n) : "memory")

__device__ __forceinline__ void ldm_x4(uint32_t& r0, uint32_t& r1,
                                       uint32_t& r2, uint32_t& r3, uint32_t a) {
    asm volatile("ldmatrix.sync.aligned.m8n8.x4.shared.b16 {%0,%1,%2,%3}, [%4];"
                 : "=r"(r0), "=r"(r1), "=r"(r2), "=r"(r3) : "r"(a));
}
__device__ __forceinline__ void ldm_x4t(uint32_t& r0, uint32_t& r1,
                                        uint32_t& r2, uint32_t& r3, uint32_t a) {
    asm volatile("ldmatrix.sync.aligned.m8n8.x4.trans.shared.b16 {%0,%1,%2,%3}, [%4];"
                 : "=r"(r0), "=r"(r1), "=r"(r2), "=r"(r3) : "r"(a));
}
__device__ __forceinline__ void mma_f16(float* c, const uint32_t* a,
                                        uint32_t b0, uint32_t b1) {
    asm volatile(
        "mma.sync.aligned.m16n8k16.row.col.f32.f16.f16.f32 "
        "{%0,%1,%2,%3}, {%4,%5,%6,%7}, {%8,%9}, {%0,%1,%2,%3};"
        : "+f"(c[0]), "+f"(c[1]), "+f"(c[2]), "+f"(c[3])
        : "r"(a[0]), "r"(a[1]), "r"(a[2]), "r"(a[3]), "r"(b0), "r"(b1));
}
__device__ __forceinline__ uint32_t h2u(__half2 v) {
    union { __half2 h; uint32_t u; } cv; cv.h = v; return cv.u;
}
__device__ __forceinline__ void store_split(__half* Ch, __half* Cl,
                                            size_t off, float v0, float v1) {
    __half h0 = __float2half(v0), h1 = __float2half(v1);
    *(__half2*)(Ch + off) = __halves2half2(h0, h1);
    *(__half2*)(Cl + off) = __halves2half2(
        __float2half(v0 - __half2float(h0)),
        __float2half(v1 - __half2float(h1)));
}
__device__ __forceinline__ void split1(float v, __half& h, __half& l) {
    h = __float2half(v);
    l = __float2half(v - __half2float(h));
}

// ==================== conversion kernels ===================================
__global__ void split_vec(const float* __restrict__ src,
                          __half* __restrict__ h,
                          __half* __restrict__ l, int n4) {
    int i = blockIdx.x * blockDim.x + threadIdx.x;
    int stride = gridDim.x * blockDim.x;
    __half2* H = (__half2*)h;
    __half2* L = (__half2*)l;
    for (; i < n4; i += stride) {
        float4 v = ((const float4*)src)[i];
        __half h0, l0, h1, l1, h2, l2, h3, l3;
        split1(v.x, h0, l0); split1(v.y, h1, l1);
        split1(v.z, h2, l2); split1(v.w, h3, l3);
        H[2*i]     = __halves2half2(h0, h1);
        H[2*i + 1] = __halves2half2(h2, h3);
        L[2*i]     = __halves2half2(l0, l1);
        L[2*i + 1] = __halves2half2(l2, l3);
    }
}

// fused transpose (hi only) for Wq|Wk|Wv -> g_Wth rows [0,2304)
__global__ void tsplit_qkv(const float* __restrict__ Wq,
                           const float* __restrict__ Wk,
                           const float* __restrict__ Wv,
                           __half* __restrict__ dh) {
    __shared__ float t[32][33];
    const float* src; int N, n0, rowOff;
    int nb = blockIdx.x;
    if (nb < 64)      { src = Wq; N = 2048; n0 = nb * 32;        rowOff = 0; }
    else if (nb < 68) { src = Wk; N = 128;  n0 = (nb - 64) * 32; rowOff = 2048; }
    else              { src = Wv; N = 128;  n0 = (nb - 68) * 32; rowOff = 2176; }
    int k0 = blockIdx.y * 32;
    int tx = threadIdx.x, ty = threadIdx.y;     // 32 x 8
    #pragma unroll
    for (int r = 0; r < 4; r++)
        t[ty + r*8][tx] = src[(size_t)(k0 + ty + r*8) * N + n0 + tx];
    __syncthreads();
    #pragma unroll
    for (int r = 0; r < 4; r++) {
        int n = n0 + ty + r*8, k = k0 + tx;
        dh[(size_t)(n + rowOff) * GK + k] = __float2half(t[tx][ty + r*8]);
    }
}

// transpose (hi only) for Wo
__global__ void tsplit(const float* __restrict__ src,
                       __half* __restrict__ dh, int N) {
    __shared__ float t[32][33];
    int n0 = blockIdx.x * 32, k0 = blockIdx.y * 32;
    int tx = threadIdx.x, ty = threadIdx.y;
    #pragma unroll
    for (int r = 0; r < 4; r++)
        t[ty + r*8][tx] = src[(size_t)(k0 + ty + r*8) * N + n0 + tx];
    __syncthreads();
    #pragma unroll
    for (int r = 0; r < 4; r++) {
        int n = n0 + ty + r*8, k = k0 + tx;
        dh[(size_t)n * GK + k] = __float2half(t[tx][ty + r*8]);
    }
}

// ==================== mma.sync 2-term fp16 GEMM ============================
// C = (Ah+Al)*Bh  (exact in A; error = A*Bl ~ 2.8e-4 RMS relative).
// CTA 128x128, 8 warps (2 in M x 4 in N), warp tile 64x32, K-chunk 32,
// 3-stage cp.async (CP_WAIT(1), prefetch-before-compute), 2 CTAs/SM.
#define KC      32
#define LDSE    40
#define ROW2    (LDSE*2)                 // 80 B
// stage rows: [0,128) A-hi | [128,256) A-lo | [256,384) B-hi
#define AL_OFF  (128*ROW2)
#define BH_OFF  (256*ROW2)
#define STAGE_B (384*ROW2)               // 30720 B
#define NSTG    3
#define GSMEM   (NSTG*STAGE_B)           // 92160 B
#define NCHUNK  (GK/KC)                  // 64

__global__ __launch_bounds__(256, 2)
void gemm_mma(const __half* __restrict__ Ah, const __half* __restrict__ Al,
              const __half* __restrict__ Bh,
              __half* __restrict__ Ch, __half* __restrict__ Cl,
              float* __restrict__ Cf, const float* __restrict__ bias, int ldc) {
    extern __shared__ char smem[];
    const uint32_t sb = smem_u32(smem);

    const int tid  = threadIdx.x;
    const int wid  = tid >> 5;
    const int lane = tid & 31;
    const int wm   = wid >> 2;
    const int wn   = wid & 3;
    const int row0 = blockIdx.y * 128;
    const int n0   = blockIdx.x * 128;

    const __half* pAh = Ah + (size_t)row0 * GK;
    const __half* pAl = Al + (size_t)row0 * GK;
    const __half* pBh = Bh + (size_t)n0 * GK;

    float acc[4][4][4];
    #pragma unroll
    for (int i = 0; i < 4; i++)
        #pragma unroll
        for (int j = 0; j < 4; j++) {
            acc[i][j][0] = 0.f; acc[i][j][1] = 0.f;
            acc[i][j][2] = 0.f; acc[i][j][3] = 0.f;
        }

    const int a_row = wm * 64 + (lane & 15);
    const int a_col = (lane >> 4) * 8;
    const int b_g   = lane >> 3;
    const int b_row = wn * 32 + ((b_g >> 1) * 8) + (lane & 7);
    const int b_col = (b_g & 1) * 8;

    // cp.async: 1536 16B chunks per stage, 6 per thread
    auto load_stage = [&](int s, int c) {
        const uint32_t st = sb + s * STAGE_B;
        const int k0 = c * KC;
        #pragma unroll
        for (int it = 0; it < 6; ++it) {
            int f = tid + it * 256;          // 0..1535
            int r = f >> 2;                  // smem row 0..383
            int c16 = f & 3;
            uint32_t so = (uint32_t)(r * ROW2 + c16 * 16);
            const __half* src;
            if (r < 128)      src = pAh + (size_t)r * GK + k0 + c16 * 8;
            else if (r < 256) src = pAl + (size_t)(r - 128) * GK + k0 + c16 * 8;
            else              src = pBh + (size_t)(r - 256) * GK + k0 + c16 * 8;
            cp_async16(st + so, src);
        }
        CP_COMMIT();
    };

    load_stage(0, 0);
    load_stage(1, 1);

    int s = 0;                               // stage of chunk c
    for (int c = 0; c < NCHUNK; ++c) {
        CP_WAIT(1);
        __syncthreads();
        if (c + 2 < NCHUNK) {
            int s2 = s + 2; if (s2 >= NSTG) s2 -= NSTG;
            load_stage(s2, c + 2);           // stage (c-1)%3: freed by the barrier
        }

        const uint32_t st = sb + s * STAGE_B;

        #pragma unroll
        for (int ks = 0; ks < 2; ++ks) {
            uint32_t bh[8];
            #pragma unroll
            for (int nb = 0; nb < 2; ++nb) {
                uint32_t off = (uint32_t)((b_row + nb*16) * ROW2
                                          + (b_col + ks*16) * 2);
                ldm_x4(bh[nb*4+0], bh[nb*4+1], bh[nb*4+2], bh[nb*4+3],
                       st + BH_OFF + off);
            }
            #pragma unroll
            for (int mi = 0; mi < 4; ++mi) {
                uint32_t ah[4], al[4];
                uint32_t off = (uint32_t)((a_row + mi*16) * ROW2
                                          + (a_col + ks*16) * 2);
                ldm_x4(ah[0], ah[1], ah[2], ah[3], st + off);
                ldm_x4(al[0], al[1], al[2], al[3], st + AL_OFF + off);
                #pragma unroll
                for (int ni = 0; ni < 4; ++ni) {
                    mma_f16(acc[mi][ni], ah, bh[ni*2], bh[ni*2+1]);
                    mma_f16(acc[mi][ni], al, bh[ni*2], bh[ni*2+1]);
                }
            }
        }
        if (++s == NSTG) s = 0;
    }

    const int er = lane >> 2;
    const int ec = (lane & 3) * 2;
    #pragma unroll
    for (int mi = 0; mi < 4; ++mi) {
        #pragma unroll
        for (int ni = 0; ni < 4; ++ni) {
            int gr = row0 + wm*64 + mi*16 + er;
            int gc = n0 + wn*32 + ni*8 + ec;
            if (Cf) {
                float bx = 0.f, by = 0.f;
                if (bias) { bx = bias[gc]; by = bias[gc + 1]; }
                float2 v0 = make_float2(acc[mi][ni][0] + bx, acc[mi][ni][1] + by);
                float2 v1 = make_float2(acc[mi][ni][2] + bx, acc[mi][ni][3] + by);
                *(float2*)&Cf[(size_t)gr * ldc + gc]       = v0;
                *(float2*)&Cf[(size_t)(gr + 8) * ldc + gc] = v1;
            } else {
                store_split(Ch, Cl, (size_t)gr * ldc + gc,
                            acc[mi][ni][0], acc[mi][ni][1]);
                store_split(Ch, Cl, (size_t)(gr + 8) * ldc + gc,
                            acc[mi][ni][2], acc[mi][ni][3]);
            }
        }
    }
}

// ==================== tensor-core causal MQA flash attention ===============
// Per CTA: (b, h, 256-row Q tile). 8 warps x 32 Q rows.
// S = (Qh+Ql)*Kh (2-term). PV = Ph*Vh (1-term; error budget spent here).
// KV tiles of 32 keys (Kh|Vh), 3-stage pipeline.
#define LDA     136
#define ROWB    (LDA*2)                  // 272 B
#define QL_OFF  (256*ROWB)
#define KV0     (512*ROWB)
#define AVH     (32*ROWB)                // Vh offset within stage
#define KVSTAGE (64*ROWB)
#define ATT_SMEM (KV0 + 3*KVSTAGE)       // 191488 B

__global__ __launch_bounds__(256, 1)
void attn_mma() {
    extern __shared__ char smc[];
    const uint32_t sb = smem_u32(smc);
    const int tid = threadIdx.x, w = tid >> 5, lane = tid & 31;
    const int qt = blockIdx.x, h = blockIdx.y, b = blockIdx.z;
    const int q0 = qt * 256;
    const size_t qrow = (size_t)(b * TLEN + q0);

    auto load_kv = [&](int jt, int s) {
        const size_t krow = (size_t)(b * TLEN + jt * 32);
        const uint32_t base = sb + KV0 + s * KVSTAGE;
        #pragma unroll
        for (int it = 0; it < 4; ++it) {
            int f = tid + it * 256;          // 0..1023
            int arr = f >> 9;                // 0 Kh, 1 Vh
            int r   = (f >> 4) & 31;
            int c   = f & 15;
            const __half* src = g_Ch + (krow + r) * NQKV
                                + (arr ? 2176 : 2048) + c * 8;
            cp_async16(base + arr * AVH + r * ROWB + c * 16, src);
        }
        CP_COMMIT();
    };

    // ---- prefetch Q tile (256 rows hi+lo) + first two KV tiles ----
    #pragma unroll
    for (int it = 0; it < 32; ++it) {
        int f = tid + it * 256;              // 0..8191
        int arr = f >> 12;                   // 0=hi 1=lo
        int r   = (f >> 4) & 255;
        int c   = f & 15;
        const __half* src = (arr ? g_Cl : g_Ch)
            + (qrow + r) * NQKV + h * DH + c * 8;
        cp_async16(sb + arr * QL_OFF + r * ROWB + c * 16, src);
    }
    load_kv(0, 0);   // commits Q + KV0 together
    load_kv(1, 1);

    const int bg = lane >> 3;
    const uint32_t qa = sb + (32*w + (lane & 15)) * ROWB + ((lane >> 4) * 8) * 2;
    const uint32_t koff = (((bg >> 1) * 8) + (lane & 7)) * ROWB + ((bg & 1) * 8) * 2;
    const uint32_t voff = (((bg & 1) * 8) + (lane & 7)) * ROWB + ((bg >> 1) * 8) * 2;

    float O[2][16][4];
    #pragma unroll
    for (int mi = 0; mi < 2; mi++)
        #pragma unroll
        for (int i = 0; i < 16; i++) {
            O[mi][i][0]=0.f; O[mi][i][1]=0.f; O[mi][i][2]=0.f; O[mi][i][3]=0.f;
        }
    float m[2][2], l[2][2];
    m[0][0]=m[0][1]=m[1][0]=m[1][1] = -1e30f;
    l[0][0]=l[0][1]=l[1][0]=l[1][1] = 0.f;
    const float scale = 0.08838834764831845f;   // 1/sqrt(128)

    const int ntile = 8 * qt + 8;
    int sst = 0;
    for (int jt = 0; jt < ntile; ++jt) {
        CP_WAIT(1);
        __syncthreads();
        if (jt + 2 < ntile) {
            int s2 = sst + 2; if (s2 >= 3) s2 -= 3;
            load_kv(jt + 2, s2);
        }
        const uint32_t st = sb + KV0 + sst * KVSTAGE;
        if (++sst == 3) sst = 0;

        if (jt * 32 > q0 + 32*w + 31) continue;   // fully masked for this warp

        const uint32_t ka = st + koff;
        const uint32_t va = st + AVH + voff;

        // ---- S = Q K^T (2-term: (Qh+Ql)*Kh) ----
        float S[2][4][4];
        #pragma unroll
        for (int mi = 0; mi < 2; mi++)
            #pragma unroll
            for (int i = 0; i < 4; i++) {
                S[mi][i][0]=0.f; S[mi][i][1]=0.f; S[mi][i][2]=0.f; S[mi][i][3]=0.f;
            }

        #pragma unroll
        for (int ks = 0; ks < 8; ++ks) {
            uint32_t ah[2][4], al[2][4];
            #pragma unroll
            for (int mi = 0; mi < 2; ++mi) {
                ldm_x4(ah[mi][0], ah[mi][1], ah[mi][2], ah[mi][3],
                       qa + mi*(16*ROWB) + ks*32);
                ldm_x4(al[mi][0], al[mi][1], al[mi][2], al[mi][3],
                       qa + QL_OFF + mi*(16*ROWB) + ks*32);
            }
            #pragma unroll
            for (int nn = 0; nn < 2; ++nn) {
                uint32_t kh[4];
                ldm_x4(kh[0], kh[1], kh[2], kh[3],
                       ka + nn*(16*ROWB) + ks*32);
                #pragma unroll
                for (int mi = 0; mi < 2; ++mi) {
                    mma_f16(S[mi][2*nn],   ah[mi], kh[0], kh[1]);
                    mma_f16(S[mi][2*nn],   al[mi], kh[0], kh[1]);
                    mma_f16(S[mi][2*nn+1], ah[mi], kh[2], kh[3]);
                    mma_f16(S[mi][2*nn+1], al[mi], kh[2], kh[3]);
                }
            }
        }

        // ---- scale + causal mask + online softmax ----
        const bool edge = (jt * 32 + 31 > q0 + 32*w);
        const int cb = jt*32 + 2*(lane & 3);
        uint32_t phi[2][2][4];
        #pragma unroll
        for (int mi = 0; mi < 2; ++mi) {
            const int gr0 = q0 + 32*w + 16*mi + (lane >> 2);
            #pragma unroll
            for (int nt = 0; nt < 4; ++nt) {
                S[mi][nt][0] *= scale; S[mi][nt][1] *= scale;
                S[mi][nt][2] *= scale; S[mi][nt][3] *= scale;
            }
            if (edge) {
                #pragma unroll
                for (int nt = 0; nt < 4; ++nt) {
                    int gk = cb + 8*nt;
                    if (gk     > gr0)     S[mi][nt][0] = -1e30f;
                    if (gk + 1 > gr0)     S[mi][nt][1] = -1e30f;
                    if (gk     > gr0 + 8) S[mi][nt][2] = -1e30f;
                    if (gk + 1 > gr0 + 8) S[mi][nt][3] = -1e30f;
                }
            }

            float rm0 = -1e30f, rm1 = -1e30f;
            #pragma unroll
            for (int nt = 0; nt < 4; ++nt) {
                rm0 = fmaxf(rm0, fmaxf(S[mi][nt][0], S[mi][nt][1]));
                rm1 = fmaxf(rm1, fmaxf(S[mi][nt][2], S[mi][nt][3]));
            }
            rm0 = fmaxf(rm0, __shfl_xor_sync(0xffffffffu, rm0, 1));
            rm0 = fmaxf(rm0, __shfl_xor_sync(0xffffffffu, rm0, 2));
            rm1 = fmaxf(rm1, __shfl_xor_sync(0xffffffffu, rm1, 1));
            rm1 = fmaxf(rm1, __shfl_xor_sync(0xffffffffu, rm1, 2));
            float mn0 = fmaxf(m[mi][0], rm0), mn1 = fmaxf(m[mi][1], rm1);
            float a0 = __expf(m[mi][0] - mn0), a1 = __expf(m[mi][1] - mn1);
            m[mi][0] = mn0; m[mi][1] = mn1;

            float rs0 = 0.f, rs1 = 0.f;
            #pragma unroll
            for (int nt = 0; nt < 4; ++nt) {
                float p0 = __expf(S[mi][nt][0] - mn0), p1 = __expf(S[mi][nt][1] - mn0);
                float p2 = __expf(S[mi][nt][2] - mn1), p3 = __expf(S[mi][nt][3] - mn1);
                rs0 += p0 + p1;  rs1 += p2 + p3;
                int ki = nt >> 1, sl = (nt & 1) * 2;
                phi[mi][ki][sl+0] = h2u(__halves2half2(__float2half(p0),
                                                       __float2half(p1)));
                phi[mi][ki][sl+1] = h2u(__halves2half2(__float2half(p2),
                                                       __float2half(p3)));
            }
            rs0 += __shfl_xor_sync(0xffffffffu, rs0, 1);
            rs0 += __shfl_xor_sync(0xffffffffu, rs0, 2);
            rs1 += __shfl_xor_sync(0xffffffffu, rs1, 1);
            rs1 += __shfl_xor_sync(0xffffffffu, rs1, 2);
            l[mi][0] = l[mi][0] * a0 + rs0;
            l[mi][1] = l[mi][1] * a1 + rs1;

            #pragma unroll
            for (int ni = 0; ni < 16; ++ni) {
                O[mi][ni][0] *= a0; O[mi][ni][1] *= a0;
                O[mi][ni][2] *= a1; O[mi][ni][3] *= a1;
            }
        }

        // ---- O += Ph Vh (1-term) ----
        #pragma unroll
        for (int ki = 0; ki < 2; ++ki) {
            #pragma unroll
            for (int nb = 0; nb < 8; ++nb) {
                uint32_t vh[4];
                ldm_x4t(vh[0], vh[1], vh[2], vh[3],
                        va + ki*(16*ROWB) + nb*32);
                #pragma unroll
                for (int mi = 0; mi < 2; ++mi) {
                    mma_f16(O[mi][2*nb],   phi[mi][ki], vh[0], vh[1]);
                    mma_f16(O[mi][2*nb+1], phi[mi][ki], vh[2], vh[3]);
                }
            }
        }
    }

    // ---- epilogue: normalize, split to fp16 hi/lo, store ----
    #pragma unroll
    for (int mi = 0; mi < 2; ++mi) {
        float il0 = 1.0f / l[mi][0], il1 = 1.0f / l[mi][1];
        size_t r0 = qrow + 32*w + 16*mi + (lane >> 2);
        int colb = h * DH + 2 * (lane & 3);
        #pragma unroll
        for (int ni = 0; ni < 16; ++ni) {
            int col = colb + 8 * ni;
            store_split(g_Ah, g_Al, r0 * EMB + col,
                        O[mi][ni][0] * il0, O[mi][ni][1] * il0);
            store_split(g_Ah, g_Al, (r0 + 8) * EMB + col,
                        O[mi][ni][2] * il1, O[mi][ni][3] * il1);
        }
    }
}

// ==================== launch ===============================================
extern "C" void kernel_launch(void* const* d_in, const int* in_sizes, int n_in,
                              void* d_out, int out_size) {
    const float* x  = (const float*)d_in[0];
    const float* Wq = (const float*)d_in[1];
    const float* Wk = (const float*)d_in[2];
    const float* Wv = (const float*)d_in[3];
    const float* Wo = (const float*)d_in[4];
    const float* bo = (const float*)d_in[5];
    float* out = (float*)d_out;
    (void)in_sizes; (void)n_in; (void)out_size;

    void *pXh, *pXl, *pAh, *pAl, *pWth, *pWoth, *pCh, *pCl;
    cudaGetSymbolAddress(&pXh, g_Xh);     cudaGetSymbolAddress(&pXl, g_Xl);
    cudaGetSymbolAddress(&pAh, g_Ah);     cudaGetSymbolAddress(&pAl, g_Al);
    cudaGetSymbolAddress(&pWth, g_Wth);   cudaGetSymbolAddress(&pWoth, g_Woth);
    cudaGetSymbolAddress(&pCh, g_Ch);     cudaGetSymbolAddress(&pCl, g_Cl);

    cudaFuncSetAttribute(gemm_mma, cudaFuncAttributeMaxDynamicSharedMemorySize, GSMEM);
    cudaFuncSetAttribute(attn_mma, cudaFuncAttributeMaxDynamicSharedMemorySize, ATT_SMEM);

    // 1) split x; transpose weights (hi only; QKV fused into one launch)
    split_vec<<<4096, 256>>>(x, (__half*)pXh, (__half*)pXl, MROWS * EMB / 4);
    tsplit_qkv<<<dim3(72, 64), dim3(32, 8)>>>(Wq, Wk, Wv, (__half*)pWth);
    tsplit<<<dim3(64, 64), dim3(32, 8)>>>(Wo, (__half*)pWoth, 2048);

    // 2) fused QKV projection (2-term) -> split fp16 g_Ch/g_Cl
    gemm_mma<<<dim3(NQKV / 128, MROWS / 128), 256, GSMEM>>>(
        (const __half*)pXh, (const __half*)pXl, (const __half*)pWth,
        (__half*)pCh, (__half*)pCl, nullptr, nullptr, NQKV);

    // 3) tensor-core causal MQA flash attention -> split fp16 g_Ah/g_Al
    attn_mma<<<dim3(TLEN / 256, NH, BSZ), 256, ATT_SMEM>>>();

    // 4) O-projection (2-term) with fused bias -> fp32 out
    gemm_mma<<<dim3(EMB / 128, MROWS / 128), 256, GSMEM>>>(
        (const __half*)pAh, (const __half*)pAl, (const __half*)pWoth,
        nullptr, nullptr, out, bo, EMB);
}